// round 7
// baseline (speedup 1.0000x reference)
#include <cuda_runtime.h>
#include <math.h>
#include <stdint.h>

#define NN 50000
#define EE 800000
#define FF 128
#define HH 8
#define LL 4

#define SCAN_B 256
#define SCAN_NB ((NN + SCAN_B - 1) / SCAN_B)   // 196

// ---------------- scratch (static device allocations; no cudaMalloc) ----------------
__device__ float g_Q[NN * FF];
__device__ float g_K[NN * FF];
__device__ float g_V[NN * FF];
__device__ float g_S[NN * FF];
__device__ float g_HA[NN * FF];
__device__ float g_HB[NN * FF];
__device__ float g_alpha_stage[EE * HH];   // fallback alpha sink if out buffer lacks room
__device__ int g_deg[NN];
__device__ int g_rowptr[NN + 1];
__device__ int g_cursor[NN];
__device__ int g_eidx[EE];   // original edge id, sorted by dst
__device__ int g_srcs[EE];   // src node, sorted by dst
__device__ int g_is64;       // 1 if edge_index is int64, 0 if int32
__device__ int g_blocksum[SCAN_NB];

// ---------------- dtype detection ----------------
__global__ void detect_kernel(const int* __restrict__ ei32) {
    int zeros = 0;
    for (int i = 0; i < 64; i++)
        if (ei32[2 * i + 1] == 0) zeros++;
    g_is64 = (zeros >= 48) ? 1 : 0;
}

__device__ __forceinline__ int load_idx(const void* eiv, long long pos) {
    if (g_is64) return (int)((const long long*)eiv)[pos];
    return ((const int*)eiv)[pos];
}

// ---------------- CSR construction ----------------
__global__ void zero_deg_kernel() {
    int i = blockIdx.x * blockDim.x + threadIdx.x;
    if (i < NN) g_deg[i] = 0;
}

__global__ void hist_kernel(const void* __restrict__ eiv) {
    int e = blockIdx.x * blockDim.x + threadIdx.x;
    if (e < EE) {
        int d = load_idx(eiv, (long long)EE + e);
        if (d >= 0 && d < NN) atomicAdd(&g_deg[d], 1);
    }
}

// multiblock scan: reduce -> scan partials -> local scan + offset
__global__ void __launch_bounds__(SCAN_B) reduce_kernel() {
    int tid = threadIdx.x, lane = tid & 31, wid = tid >> 5;
    int i = blockIdx.x * SCAN_B + tid;
    int v = (i < NN) ? g_deg[i] : 0;
#pragma unroll
    for (int o = 16; o > 0; o >>= 1) v += __shfl_down_sync(0xffffffffu, v, o);
    __shared__ int ws[8];
    if (lane == 0) ws[wid] = v;
    __syncthreads();
    if (tid == 0) {
        int s = 0;
#pragma unroll
        for (int w = 0; w < 8; w++) s += ws[w];
        g_blocksum[blockIdx.x] = s;
    }
}

__device__ __forceinline__ int block_incl_scan(int v, int tid) {
    int lane = tid & 31, wid = tid >> 5;
    int x = v;
#pragma unroll
    for (int o = 1; o < 32; o <<= 1) {
        int t = __shfl_up_sync(0xffffffffu, x, o);
        if (lane >= o) x += t;
    }
    __shared__ int wsum[8];
    if (lane == 31) wsum[wid] = x;
    __syncthreads();
    if (wid == 0) {
        int y = (lane < 8) ? wsum[lane] : 0;
#pragma unroll
        for (int o = 1; o < 8; o <<= 1) {
            int t = __shfl_up_sync(0xffffffffu, y, o);
            if (lane >= o) y += t;
        }
        if (lane < 8) wsum[lane] = y;
    }
    __syncthreads();
    return x + ((wid > 0) ? wsum[wid - 1] : 0);
}

__global__ void __launch_bounds__(SCAN_B) scanpart_kernel() {
    int tid = threadIdx.x;
    int v = (tid < SCAN_NB) ? g_blocksum[tid] : 0;
    int incl = block_incl_scan(v, tid);
    if (tid < SCAN_NB) g_blocksum[tid] = incl - v;  // exclusive
}

__global__ void __launch_bounds__(SCAN_B) scanfinal_kernel() {
    int tid = threadIdx.x;
    int i = blockIdx.x * SCAN_B + tid;
    int v = (i < NN) ? g_deg[i] : 0;
    int incl = block_incl_scan(v, tid);
    int off = g_blocksum[blockIdx.x];
    if (i < NN) {
        int e = off + incl - v;
        g_rowptr[i] = e;
        g_cursor[i] = e;
    }
    if (i == NN - 1) g_rowptr[NN] = off + incl;
}

__global__ void scatter_kernel(const void* __restrict__ eiv) {
    int e = blockIdx.x * blockDim.x + threadIdx.x;
    if (e < EE) {
        int s = load_idx(eiv, e);
        int d = load_idx(eiv, (long long)EE + e);
        if (d >= 0 && d < NN && s >= 0 && s < NN) {
            int p = atomicAdd(&g_cursor[d], 1);
            if (p >= 0 && p < EE) {
                g_eidx[p] = e;
                g_srcs[p] = s;
            }
        }
    }
}

// ---------------- tensor-core GEMM via 3xTF32 mma.sync ----------------
// O = X @ W + b. BM=128, BN=128 (one of 4 W per blockIdx.y), BK=16, 256 threads.
// 8 warps in 2(M)x4(N): warp tile 64x32 = 4 m-tiles (m16) x 4 n-tiles (n8).
// x = hi + lo (tf32 each), w = hi + lo; acc += hi*hi + hi*lo + lo*hi (fp32 accum).

__device__ __forceinline__ uint32_t f2tf32(float f) {
    uint32_t u;
    asm("cvt.rna.tf32.f32 %0, %1;" : "=r"(u) : "f"(f));
    return u;
}

__device__ __forceinline__ void mma_tf32(float* c, const uint32_t* a, const uint32_t* b) {
    asm volatile(
        "mma.sync.aligned.m16n8k8.row.col.f32.tf32.tf32.f32 "
        "{%0,%1,%2,%3}, {%4,%5,%6,%7}, {%8,%9}, {%0,%1,%2,%3};"
        : "+f"(c[0]), "+f"(c[1]), "+f"(c[2]), "+f"(c[3])
        : "r"(a[0]), "r"(a[1]), "r"(a[2]), "r"(a[3]), "r"(b[0]), "r"(b[1]));
}

__global__ void __launch_bounds__(256) gemm_kernel(
    const float* __restrict__ x_in, int hin_sel,
    const float* __restrict__ W0, const float* __restrict__ W1,
    const float* __restrict__ W2, const float* __restrict__ W3,
    const float* __restrict__ b0, const float* __restrict__ b1,
    const float* __restrict__ b2, const float* __restrict__ b3)
{
    const float* X = (hin_sel == 0) ? x_in : ((hin_sel == 1) ? g_HA : g_HB);
    int which = blockIdx.y;
    const float* W = (which == 0) ? W0 : ((which == 1) ? W1 : ((which == 2) ? W2 : W3));
    const float* b = (which == 0) ? b0 : ((which == 1) ? b1 : ((which == 2) ? b2 : b3));
    float* O = (which == 0) ? g_Q : ((which == 1) ? g_K : ((which == 2) ? g_V : g_S));

    __shared__ float2 Xs[16][129];  // [k][m] {hi,lo}
    __shared__ float2 Ws[16][129];  // [k][n] {hi,lo}

    int tid = threadIdx.x;
    int row0 = blockIdx.x * 128;
    int wid = tid >> 5, lane = tid & 31;
    int wm = (wid >> 2) * 64;   // warp M offset (0 or 64)
    int wn = (wid & 3) * 32;    // warp N offset
    int g = lane >> 2, tg = lane & 3;

    float c[4][4][4];
#pragma unroll
    for (int mt = 0; mt < 4; mt++)
#pragma unroll
        for (int nt = 0; nt < 4; nt++)
#pragma unroll
            for (int r = 0; r < 4; r++) c[mt][nt][r] = 0.f;

    for (int kc = 0; kc < FF; kc += 16) {
        // X chunk: 128 rows x 16 k  (512 float4 loads / 256 threads = 2 reps)
#pragma unroll
        for (int rep = 0; rep < 2; rep++) {
            int linear = tid + rep * 256;     // 0..511
            int m = linear >> 2;              // 0..127
            int f4 = linear & 3;              // 0..3
            float4 v = make_float4(0.f, 0.f, 0.f, 0.f);
            if (row0 + m < NN)
                v = *(const float4*)(X + (size_t)(row0 + m) * FF + kc + f4 * 4);
            float vals[4] = {v.x, v.y, v.z, v.w};
#pragma unroll
            for (int j = 0; j < 4; j++) {
                uint32_t hi = f2tf32(vals[j]);
                float hif = __uint_as_float(hi);
                uint32_t lo = f2tf32(vals[j] - hif);
                Xs[f4 * 4 + j][m] = make_float2(hif, __uint_as_float(lo));
            }
        }
        // W chunk: 16 k x 128 n
#pragma unroll
        for (int rep = 0; rep < 2; rep++) {
            int linear = tid + rep * 256;
            int k = linear >> 5;              // 0..15
            int f4 = linear & 31;             // 0..31
            float4 v = *(const float4*)(W + (size_t)(kc + k) * FF + f4 * 4);
            float vals[4] = {v.x, v.y, v.z, v.w};
#pragma unroll
            for (int j = 0; j < 4; j++) {
                uint32_t hi = f2tf32(vals[j]);
                float hif = __uint_as_float(hi);
                uint32_t lo = f2tf32(vals[j] - hif);
                Ws[k][f4 * 4 + j] = make_float2(hif, __uint_as_float(lo));
            }
        }
        __syncthreads();

#pragma unroll
        for (int ks = 0; ks < 2; ks++) {
            int k = ks * 8;
            // B fragments (col layout): b[0]=B[k=tg][n=g], b[1]=B[k=tg+4][n=g]
            uint32_t bh[4][2], bl[4][2];
#pragma unroll
            for (int nt = 0; nt < 4; nt++) {
                float2 t0 = Ws[k + tg][wn + nt * 8 + g];
                float2 t1 = Ws[k + tg + 4][wn + nt * 8 + g];
                bh[nt][0] = __float_as_uint(t0.x); bl[nt][0] = __float_as_uint(t0.y);
                bh[nt][1] = __float_as_uint(t1.x); bl[nt][1] = __float_as_uint(t1.y);
            }
#pragma unroll
            for (int mt = 0; mt < 4; mt++) {
                int m = wm + mt * 16;
                // A fragments (row layout): a0=(g,tg) a1=(g+8,tg) a2=(g,tg+4) a3=(g+8,tg+4)
                float2 a0 = Xs[k + tg][m + g];
                float2 a1 = Xs[k + tg][m + g + 8];
                float2 a2 = Xs[k + tg + 4][m + g];
                float2 a3 = Xs[k + tg + 4][m + g + 8];
                uint32_t ah[4] = {__float_as_uint(a0.x), __float_as_uint(a1.x),
                                  __float_as_uint(a2.x), __float_as_uint(a3.x)};
                uint32_t al[4] = {__float_as_uint(a0.y), __float_as_uint(a1.y),
                                  __float_as_uint(a2.y), __float_as_uint(a3.y)};
#pragma unroll
                for (int nt = 0; nt < 4; nt++) {
                    mma_tf32(c[mt][nt], ah, bh[nt]);
                    mma_tf32(c[mt][nt], ah, bl[nt]);
                    mma_tf32(c[mt][nt], al, bh[nt]);
                }
            }
        }
        __syncthreads();
    }

    // epilogue: c0=(g, tg*2) c1=(g, tg*2+1) c2=(g+8, tg*2) c3=(g+8, tg*2+1)
#pragma unroll
    for (int mt = 0; mt < 4; mt++) {
#pragma unroll
        for (int nt = 0; nt < 4; nt++) {
            int col = wn + nt * 8 + tg * 2;
            float bx = b[col], by = b[col + 1];
            int row = row0 + wm + mt * 16 + g;
            if (row < NN) {
                float2* p = (float2*)(O + (size_t)row * FF + col);
                *p = make_float2(c[mt][nt][0] + bx, c[mt][nt][1] + by);
            }
            if (row + 8 < NN) {
                float2* p = (float2*)(O + (size_t)(row + 8) * FF + col);
                *p = make_float2(c[mt][nt][2] + bx, c[mt][nt][3] + by);
            }
        }
    }
}

// ---------------- edge phase: one warp per destination node, online softmax ----------------
__global__ void __launch_bounds__(256) edge_kernel(
    int hout_sel, float* __restrict__ out_h, float* __restrict__ alpha_out, int apply_gelu)
{
    int gw = (blockIdx.x * blockDim.x + threadIdx.x) >> 5;
    int lane = threadIdx.x & 31;
    if (gw >= NN) return;
    int n = gw;
    int beg = g_rowptr[n];
    int end = g_rowptr[n + 1];

    float4 q4 = ((const float4*)(g_Q + (size_t)n * FF))[lane];
    int h = lane >> 2;  // head id (4 lanes per head, D=16 -> 4 floats/lane)

    float m = -3.0e38f;
    float denom = 0.f;
    float4 acc = make_float4(0.f, 0.f, 0.f, 0.f);

    for (int p = beg; p < end; p++) {
        int s = g_srcs[p];
        float4 k4 = ((const float4*)(g_K + (size_t)s * FF))[lane];
        float d = q4.x * k4.x + q4.y * k4.y + q4.z * k4.z + q4.w * k4.w;
        d += __shfl_xor_sync(0xffffffffu, d, 1);
        d += __shfl_xor_sync(0xffffffffu, d, 2);
        float alpha = d * 0.25f;  // 1/sqrt(16)
        if ((lane & 3) == 0) alpha_out[(size_t)g_eidx[p] * HH + h] = alpha;  // raw, rewritten below
        float4 v4 = ((const float4*)(g_V + (size_t)s * FF))[lane];
        float mn = fmaxf(m, alpha);
        float sc = __expf(m - mn);
        float pe = __expf(alpha - mn);
        denom = denom * sc + pe;
        acc.x = acc.x * sc + pe * v4.x;
        acc.y = acc.y * sc + pe * v4.y;
        acc.z = acc.z * sc + pe * v4.z;
        acc.w = acc.w * sc + pe * v4.w;
        m = mn;
    }

    float inv = (end > beg && denom > 0.f) ? 1.f / denom : 0.f;

    // normalize per-edge coefficients (same lane wrote the raw value -> same-thread RAW order ok)
    for (int p = beg; p < end; p++) {
        if ((lane & 3) == 0) {
            size_t eo = (size_t)g_eidx[p] * HH + h;
            float a = alpha_out[eo];
            alpha_out[eo] = __expf(a - m) * inv;
        }
    }

    float* HO = (hout_sel == 0) ? g_HA : ((hout_sel == 1) ? g_HB : out_h);
    float4 s4 = ((const float4*)(g_S + (size_t)n * FF))[lane];
    float4 o;
    o.x = acc.x * inv + s4.x;
    o.y = acc.y * inv + s4.y;
    o.z = acc.z * inv + s4.z;
    o.w = acc.w * inv + s4.w;
    if (apply_gelu) {
        o.x = 0.5f * o.x * (1.f + erff(o.x * 0.70710678118654752f));
        o.y = 0.5f * o.y * (1.f + erff(o.y * 0.70710678118654752f));
        o.z = 0.5f * o.z * (1.f + erff(o.z * 0.70710678118654752f));
        o.w = 0.5f * o.w * (1.f + erff(o.w * 0.70710678118654752f));
    }
    ((float4*)(HO + (size_t)n * FF))[lane] = o;
}

// small helper to fetch the staging symbol address once (host-side, no allocation)
static float* alpha_stage_ptr() {
    void* p = nullptr;
    cudaGetSymbolAddress(&p, g_alpha_stage);
    return (float*)p;
}

// ---------------- launch ----------------
extern "C" void kernel_launch(void* const* d_in, const int* in_sizes, int n_in,
                              void* d_out, int out_size)
{
    const float* x = (const float*)d_in[0];
    const void* ei = (const void*)d_in[1];
    const float* Wq = (const float*)d_in[2];
    const float* bq = (const float*)d_in[3];
    const float* Wk = (const float*)d_in[4];
    const float* bk = (const float*)d_in[5];
    const float* Wv = (const float*)d_in[6];
    const float* bv = (const float*)d_in[7];
    const float* Ws = (const float*)d_in[8];
    const float* bs = (const float*)d_in[9];
    float* out = (float*)d_out;

    const long long full_elems = (long long)NN * FF + (long long)LL * EE * HH;
    bool alphas_in_out = ((long long)out_size >= full_elems);
    float* stage = alphas_in_out ? nullptr : alpha_stage_ptr();

    // edge_index dtype detection + CSR build (reused by all layers)
    detect_kernel<<<1, 1>>>((const int*)ei);
    zero_deg_kernel<<<(NN + 255) / 256, 256>>>();
    hist_kernel<<<(EE + 255) / 256, 256>>>(ei);
    reduce_kernel<<<SCAN_NB, SCAN_B>>>();
    scanpart_kernel<<<1, SCAN_B>>>();
    scanfinal_kernel<<<SCAN_NB, SCAN_B>>>();
    scatter_kernel<<<(EE + 255) / 256, 256>>>(ei);

    dim3 ggrid((NN + 127) / 128, 4);
    int eblocks = (NN * 32 + 255) / 256;

    // layer l: hin_sel  (0=x, 1=g_HA, 2=g_HB), hout_sel (0=g_HA, 1=g_HB, 2=d_out)
    const int hin_sel[LL]  = {0, 1, 2, 1};
    const int hout_sel[LL] = {0, 1, 0, 2};

    for (int l = 0; l < LL; l++) {
        size_t wofs = (size_t)l * FF * FF;
        size_t bofs = (size_t)l * FF;
        gemm_kernel<<<ggrid, 256>>>(x, hin_sel[l],
                                    Wq + wofs, Wk + wofs, Wv + wofs, Ws + wofs,
                                    bq + bofs, bk + bofs, bv + bofs, bs + bofs);
        float* alpha_out = alphas_in_out
            ? (out + (size_t)NN * FF + (size_t)l * EE * HH)
            : stage;
        edge_kernel<<<eblocks, 256>>>(hout_sel[l], out, alpha_out, (l < LL - 1) ? 1 : 0);
    }
}

// round 9
// speedup vs baseline: 1.5645x; 1.5645x over previous
#include <cuda_runtime.h>
#include <cuda_bf16.h>
#include <math.h>
#include <stdint.h>

#define NN 50000
#define EE 800000
#define FF 128
#define HH 8
#define LL 4

#define SCAN_B 256
#define SCAN_NB ((NN + SCAN_B - 1) / SCAN_B)   // 196
#define MTILES ((NN + 127) / 128)              // 391

// smem tile geometry: 128 rows x 128 bf16 cols, padded to 136 (272B rows)
#define SJ 136
#define TILE_BYTES (128 * SJ * 2)              // 34816
#define SMEM_TOTAL (4 * TILE_BYTES)            // 139264

// ---------------- scratch (static device allocations; no cudaMalloc) ----------------
__device__ float g_Q[NN * FF];
__device__ float g_K[NN * FF];
__device__ float g_V[NN * FF];
__device__ float g_S[NN * FF];
__device__ float g_HA[NN * FF];
__device__ float g_HB[NN * FF];
__device__ float g_alpha_stage[EE * HH];
__device__ __nv_bfloat16 g_X0[NN * FF];        // hi split of layer input
__device__ __nv_bfloat16 g_X1[NN * FF];        // lo split
__device__ __nv_bfloat16 g_B0[4 * FF * FF];    // W^T hi split, [which][n][k]
__device__ __nv_bfloat16 g_B1[4 * FF * FF];    // W^T lo split
__device__ int g_deg[NN];
__device__ int g_rowptr[NN + 1];
__device__ int g_cursor[NN];
__device__ int g_eidx[EE];
__device__ int g_srcs[EE];
__device__ int g_is64;
__device__ int g_blocksum[SCAN_NB];

// ---------------- dtype detection ----------------
__global__ void detect_kernel(const int* __restrict__ ei32) {
    int zeros = 0;
    for (int i = 0; i < 64; i++)
        if (ei32[2 * i + 1] == 0) zeros++;
    g_is64 = (zeros >= 48) ? 1 : 0;
}

__device__ __forceinline__ int load_idx(const void* eiv, long long pos) {
    if (g_is64) return (int)((const long long*)eiv)[pos];
    return ((const int*)eiv)[pos];
}

// ---------------- CSR construction ----------------
__global__ void zero_deg_kernel() {
    int i = blockIdx.x * blockDim.x + threadIdx.x;
    if (i < NN) g_deg[i] = 0;
}

__global__ void hist_kernel(const void* __restrict__ eiv) {
    int e = blockIdx.x * blockDim.x + threadIdx.x;
    if (e < EE) {
        int d = load_idx(eiv, (long long)EE + e);
        if (d >= 0 && d < NN) atomicAdd(&g_deg[d], 1);
    }
}

__global__ void __launch_bounds__(SCAN_B) reduce_kernel() {
    int tid = threadIdx.x, lane = tid & 31, wid = tid >> 5;
    int i = blockIdx.x * SCAN_B + tid;
    int v = (i < NN) ? g_deg[i] : 0;
#pragma unroll
    for (int o = 16; o > 0; o >>= 1) v += __shfl_down_sync(0xffffffffu, v, o);
    __shared__ int ws[8];
    if (lane == 0) ws[wid] = v;
    __syncthreads();
    if (tid == 0) {
        int s = 0;
#pragma unroll
        for (int w = 0; w < 8; w++) s += ws[w];
        g_blocksum[blockIdx.x] = s;
    }
}

__device__ __forceinline__ int block_incl_scan(int v, int tid) {
    int lane = tid & 31, wid = tid >> 5;
    int x = v;
#pragma unroll
    for (int o = 1; o < 32; o <<= 1) {
        int t = __shfl_up_sync(0xffffffffu, x, o);
        if (lane >= o) x += t;
    }
    __shared__ int wsum[8];
    if (lane == 31) wsum[wid] = x;
    __syncthreads();
    if (wid == 0) {
        int y = (lane < 8) ? wsum[lane] : 0;
#pragma unroll
        for (int o = 1; o < 8; o <<= 1) {
            int t = __shfl_up_sync(0xffffffffu, y, o);
            if (lane >= o) y += t;
        }
        if (lane < 8) wsum[lane] = y;
    }
    __syncthreads();
    return x + ((wid > 0) ? wsum[wid - 1] : 0);
}

__global__ void __launch_bounds__(SCAN_B) scanpart_kernel() {
    int tid = threadIdx.x;
    int v = (tid < SCAN_NB) ? g_blocksum[tid] : 0;
    int incl = block_incl_scan(v, tid);
    if (tid < SCAN_NB) g_blocksum[tid] = incl - v;
}

__global__ void __launch_bounds__(SCAN_B) scanfinal_kernel() {
    int tid = threadIdx.x;
    int i = blockIdx.x * SCAN_B + tid;
    int v = (i < NN) ? g_deg[i] : 0;
    int incl = block_incl_scan(v, tid);
    int off = g_blocksum[blockIdx.x];
    if (i < NN) {
        int e = off + incl - v;
        g_rowptr[i] = e;
        g_cursor[i] = e;
    }
    if (i == NN - 1) g_rowptr[NN] = off + incl;
}

__global__ void scatter_kernel(const void* __restrict__ eiv) {
    int e = blockIdx.x * blockDim.x + threadIdx.x;
    if (e < EE) {
        int s = load_idx(eiv, e);
        int d = load_idx(eiv, (long long)EE + e);
        if (d >= 0 && d < NN && s >= 0 && s < NN) {
            int p = atomicAdd(&g_cursor[d], 1);
            if (p >= 0 && p < EE) {
                g_eidx[p] = e;
                g_srcs[p] = s;
            }
        }
    }
}

// ---------------- split kernels (fp32 -> hi/lo bf16) ----------------
__device__ __forceinline__ void split_bf16(float v, __nv_bfloat16& hi, __nv_bfloat16& lo) {
    hi = __float2bfloat16_rn(v);
    lo = __float2bfloat16_rn(v - __bfloat162float(hi));
}

__global__ void __launch_bounds__(256) splitx_kernel(const float* __restrict__ xext, int hin_sel) {
    const float* X = (hin_sel == 0) ? xext : ((hin_sel == 1) ? g_HA : g_HB);
    int i = blockIdx.x * blockDim.x + threadIdx.x;   // float4 index
    if (i < NN * FF / 4) {
        float4 v = ((const float4*)X)[i];
        __nv_bfloat16 h0, l0, h1, l1, h2, l2, h3, l3;
        split_bf16(v.x, h0, l0); split_bf16(v.y, h1, l1);
        split_bf16(v.z, h2, l2); split_bf16(v.w, h3, l3);
        ((__nv_bfloat162*)g_X0)[2 * i]     = __nv_bfloat162(h0, h1);
        ((__nv_bfloat162*)g_X0)[2 * i + 1] = __nv_bfloat162(h2, h3);
        ((__nv_bfloat162*)g_X1)[2 * i]     = __nv_bfloat162(l0, l1);
        ((__nv_bfloat162*)g_X1)[2 * i + 1] = __nv_bfloat162(l2, l3);
    }
}

// transpose + split: B[which][n][k] = W_which[k][n]
__global__ void __launch_bounds__(256) splitw_kernel(
    const float* __restrict__ W0, const float* __restrict__ W1,
    const float* __restrict__ W2, const float* __restrict__ W3)
{
    int idx = blockIdx.x * blockDim.x + threadIdx.x;  // which*16384 + k*128 + n
    if (idx < 4 * FF * FF) {
        int which = idx >> 14;
        int r = idx & 16383;
        int k = r >> 7, n = r & 127;
        const float* W = (which == 0) ? W0 : ((which == 1) ? W1 : ((which == 2) ? W2 : W3));
        float v = W[r];
        __nv_bfloat16 hi, lo;
        split_bf16(v, hi, lo);
        g_B0[(which << 14) + n * FF + k] = hi;
        g_B1[(which << 14) + n * FF + k] = lo;
    }
}

// ---------------- bf16 mma.sync GEMM: O = X @ W + b via 3-product split ----------------
__device__ __forceinline__ void mma_bf16(float* c, const uint32_t* a, const uint32_t* b) {
    asm volatile(
        "mma.sync.aligned.m16n8k16.row.col.f32.bf16.bf16.f32 "
        "{%0,%1,%2,%3}, {%4,%5,%6,%7}, {%8,%9}, {%0,%1,%2,%3};"
        : "+f"(c[0]), "+f"(c[1]), "+f"(c[2]), "+f"(c[3])
        : "r"(a[0]), "r"(a[1]), "r"(a[2]), "r"(a[3]), "r"(b[0]), "r"(b[1]));
}

// grid (MTILES, 4), 256 threads, 139 KB dynamic smem, 1 CTA/SM.
// 8 warps as 2(M) x 4(N): warp tile 64x32 = 4 m-tiles (m16) x 4 n-tiles (n8), k16 steps.
__global__ void __launch_bounds__(256, 1) gemm_mma_kernel(
    const float* __restrict__ b0, const float* __restrict__ b1,
    const float* __restrict__ b2, const float* __restrict__ b3)
{
    extern __shared__ char smem[];
    uint32_t* A0w = (uint32_t*)smem;                       // [row][word] stride 68 words
    uint32_t* A1w = (uint32_t*)(smem + TILE_BYTES);
    uint32_t* B0w = (uint32_t*)(smem + 2 * TILE_BYTES);
    uint32_t* B1w = (uint32_t*)(smem + 3 * TILE_BYTES);
    const int WS = SJ / 2;  // 68 words per row

    int tid = threadIdx.x;
    int wid = tid >> 5, lane = tid & 31;
    int which = blockIdx.y;
    int row0 = blockIdx.x * 128;
    const float* bias = (which == 0) ? b0 : ((which == 1) ? b1 : ((which == 2) ? b2 : b3));
    float* O = (which == 0) ? g_Q : ((which == 1) ? g_K : ((which == 2) ? g_V : g_S));

    // stage tiles: A from g_X0/g_X1 rows row0..row0+127; B = W^T splits for `which`
    {
        const uint4* xa0 = (const uint4*)g_X0;
        const uint4* xa1 = (const uint4*)g_X1;
        const uint4* wb0 = (const uint4*)(g_B0 + ((size_t)which << 14));
        const uint4* wb1 = (const uint4*)(g_B1 + ((size_t)which << 14));
        const uint4 z4 = make_uint4(0u, 0u, 0u, 0u);
#pragma unroll
        for (int it = 0; it < 8; it++) {
            int i = tid + it * 256;          // 0..2047
            int row = i >> 4, c16 = i & 15;  // 16B chunk index in row
            int so = row * (SJ / 8) + c16;   // uint4 index with padding (SJ/8 = 17)
            bool ok = (row0 + row) < NN;
            size_t gi = ((size_t)(row0 + row) * FF) / 8 + c16;
            ((uint4*)A0w)[so] = ok ? xa0[gi] : z4;
            ((uint4*)A1w)[so] = ok ? xa1[gi] : z4;
            size_t bi = ((size_t)row * FF) / 8 + c16;
            ((uint4*)B0w)[so] = wb0[bi];
            ((uint4*)B1w)[so] = wb1[bi];
        }
    }
    __syncthreads();

    int wm = (wid >> 2) * 64;   // warp M offset
    int wn = (wid & 3) * 32;    // warp N offset
    int g = lane >> 2, tg = lane & 3;

    float c[4][4][4];
#pragma unroll
    for (int mt = 0; mt < 4; mt++)
#pragma unroll
        for (int nt = 0; nt < 4; nt++)
#pragma unroll
            for (int r = 0; r < 4; r++) c[mt][nt][r] = 0.f;

    // row bases (words)
    int arow[4], brow[4];
#pragma unroll
    for (int mt = 0; mt < 4; mt++) arow[mt] = (wm + mt * 16 + g) * WS;
#pragma unroll
    for (int nt = 0; nt < 4; nt++) brow[nt] = (wn + nt * 8 + g) * WS;

#pragma unroll
    for (int ks = 0; ks < 8; ks++) {
        int kw = ks * 8 + tg;    // word offset of this thread-group's k pair
        uint32_t ah[4][4], bh[4][2], al[4][4], bl[4][2];
#pragma unroll
        for (int mt = 0; mt < 4; mt++) {
            ah[mt][0] = A0w[arow[mt] + kw];
            ah[mt][1] = A0w[arow[mt] + 8 * WS + kw];
            ah[mt][2] = A0w[arow[mt] + kw + 4];
            ah[mt][3] = A0w[arow[mt] + 8 * WS + kw + 4];
        }
#pragma unroll
        for (int nt = 0; nt < 4; nt++) {
            bh[nt][0] = B0w[brow[nt] + kw];
            bh[nt][1] = B0w[brow[nt] + kw + 4];
        }
#pragma unroll
        for (int mt = 0; mt < 4; mt++)
#pragma unroll
            for (int nt = 0; nt < 4; nt++) mma_bf16(c[mt][nt], ah[mt], bh[nt]);

#pragma unroll
        for (int nt = 0; nt < 4; nt++) {
            bl[nt][0] = B1w[brow[nt] + kw];
            bl[nt][1] = B1w[brow[nt] + kw + 4];
        }
#pragma unroll
        for (int mt = 0; mt < 4; mt++)
#pragma unroll
            for (int nt = 0; nt < 4; nt++) mma_bf16(c[mt][nt], ah[mt], bl[nt]);

#pragma unroll
        for (int mt = 0; mt < 4; mt++) {
            al[mt][0] = A1w[arow[mt] + kw];
            al[mt][1] = A1w[arow[mt] + 8 * WS + kw];
            al[mt][2] = A1w[arow[mt] + kw + 4];
            al[mt][3] = A1w[arow[mt] + 8 * WS + kw + 4];
        }
#pragma unroll
        for (int mt = 0; mt < 4; mt++)
#pragma unroll
            for (int nt = 0; nt < 4; nt++) mma_bf16(c[mt][nt], al[mt], bh[nt]);
    }

    // epilogue: c0=(g, tg*2) c1=(g, tg*2+1) c2=(g+8, tg*2) c3=(g+8, tg*2+1)
#pragma unroll
    for (int mt = 0; mt < 4; mt++) {
#pragma unroll
        for (int nt = 0; nt < 4; nt++) {
            int col = wn + nt * 8 + tg * 2;
            float bx = bias[col], by = bias[col + 1];
            int row = row0 + wm + mt * 16 + g;
            if (row < NN) {
                float2* p = (float2*)(O + (size_t)row * FF + col);
                *p = make_float2(c[mt][nt][0] + bx, c[mt][nt][1] + by);
            }
            if (row + 8 < NN) {
                float2* p = (float2*)(O + (size_t)(row + 8) * FF + col);
                *p = make_float2(c[mt][nt][2] + bx, c[mt][nt][3] + by);
            }
        }
    }
}

// ---------------- edge phase: one warp per destination node, online softmax ----------------
__global__ void __launch_bounds__(256) edge_kernel(
    int hout_sel, float* __restrict__ out_h, float* __restrict__ alpha_out, int apply_gelu)
{
    int gw = (blockIdx.x * blockDim.x + threadIdx.x) >> 5;
    int lane = threadIdx.x & 31;
    if (gw >= NN) return;
    int n = gw;
    int beg = g_rowptr[n];
    int end = g_rowptr[n + 1];

    float4 q4 = ((const float4*)(g_Q + (size_t)n * FF))[lane];
    int h = lane >> 2;

    float m = -3.0e38f;
    float denom = 0.f;
    float4 acc = make_float4(0.f, 0.f, 0.f, 0.f);

    for (int p = beg; p < end; p++) {
        int s = g_srcs[p];
        float4 k4 = ((const float4*)(g_K + (size_t)s * FF))[lane];
        float d = q4.x * k4.x + q4.y * k4.y + q4.z * k4.z + q4.w * k4.w;
        d += __shfl_xor_sync(0xffffffffu, d, 1);
        d += __shfl_xor_sync(0xffffffffu, d, 2);
        float alpha = d * 0.25f;
        if ((lane & 3) == 0) alpha_out[(size_t)g_eidx[p] * HH + h] = alpha;
        float4 v4 = ((const float4*)(g_V + (size_t)s * FF))[lane];
        float mn = fmaxf(m, alpha);
        float sc = __expf(m - mn);
        float pe = __expf(alpha - mn);
        denom = denom * sc + pe;
        acc.x = acc.x * sc + pe * v4.x;
        acc.y = acc.y * sc + pe * v4.y;
        acc.z = acc.z * sc + pe * v4.z;
        acc.w = acc.w * sc + pe * v4.w;
        m = mn;
    }

    float inv = (end > beg && denom > 0.f) ? 1.f / denom : 0.f;

    for (int p = beg; p < end; p++) {
        if ((lane & 3) == 0) {
            size_t eo = (size_t)g_eidx[p] * HH + h;
            float a = alpha_out[eo];
            alpha_out[eo] = __expf(a - m) * inv;
        }
    }

    float* HO = (hout_sel == 0) ? g_HA : ((hout_sel == 1) ? g_HB : out_h);
    float4 s4 = ((const float4*)(g_S + (size_t)n * FF))[lane];
    float4 o;
    o.x = acc.x * inv + s4.x;
    o.y = acc.y * inv + s4.y;
    o.z = acc.z * inv + s4.z;
    o.w = acc.w * inv + s4.w;
    if (apply_gelu) {
        o.x = 0.5f * o.x * (1.f + erff(o.x * 0.70710678118654752f));
        o.y = 0.5f * o.y * (1.f + erff(o.y * 0.70710678118654752f));
        o.z = 0.5f * o.z * (1.f + erff(o.z * 0.70710678118654752f));
        o.w = 0.5f * o.w * (1.f + erff(o.w * 0.70710678118654752f));
    }
    ((float4*)(HO + (size_t)n * FF))[lane] = o;
}

static float* alpha_stage_ptr() {
    void* p = nullptr;
    cudaGetSymbolAddress(&p, g_alpha_stage);
    return (float*)p;
}

// ---------------- launch ----------------
extern "C" void kernel_launch(void* const* d_in, const int* in_sizes, int n_in,
                              void* d_out, int out_size)
{
    const float* x = (const float*)d_in[0];
    const void* ei = (const void*)d_in[1];
    const float* Wq = (const float*)d_in[2];
    const float* bq = (const float*)d_in[3];
    const float* Wk = (const float*)d_in[4];
    const float* bk = (const float*)d_in[5];
    const float* Wv = (const float*)d_in[6];
    const float* bv = (const float*)d_in[7];
    const float* Ws = (const float*)d_in[8];
    const float* bs = (const float*)d_in[9];
    float* out = (float*)d_out;

    // idempotent, host-side, capture-safe
    cudaFuncSetAttribute(gemm_mma_kernel, cudaFuncAttributeMaxDynamicSharedMemorySize, SMEM_TOTAL);

    const long long full_elems = (long long)NN * FF + (long long)LL * EE * HH;
    bool alphas_in_out = ((long long)out_size >= full_elems);
    float* stage = alphas_in_out ? nullptr : alpha_stage_ptr();

    detect_kernel<<<1, 1>>>((const int*)ei);
    zero_deg_kernel<<<(NN + 255) / 256, 256>>>();
    hist_kernel<<<(EE + 255) / 256, 256>>>(ei);
    reduce_kernel<<<SCAN_NB, SCAN_B>>>();
    scanpart_kernel<<<1, SCAN_B>>>();
    scanfinal_kernel<<<SCAN_NB, SCAN_B>>>();
    scatter_kernel<<<(EE + 255) / 256, 256>>>(ei);

    dim3 ggrid(MTILES, 4);
    int eblocks = (NN * 32 + 255) / 256;
    int sx_blocks = (NN * FF / 4 + 255) / 256;
    int sw_blocks = (4 * FF * FF + 255) / 256;

    const int hin_sel[LL]  = {0, 1, 2, 1};
    const int hout_sel[LL] = {0, 1, 0, 2};

    for (int l = 0; l < LL; l++) {
        size_t wofs = (size_t)l * FF * FF;
        size_t bofs = (size_t)l * FF;
        splitx_kernel<<<sx_blocks, 256>>>(x, hin_sel[l]);
        splitw_kernel<<<sw_blocks, 256>>>(Wq + wofs, Wk + wofs, Wv + wofs, Ws + wofs);
        gemm_mma_kernel<<<ggrid, 256, SMEM_TOTAL>>>(bq + bofs, bk + bofs, bv + bofs, bs + bofs);
        float* alpha_out = alphas_in_out
            ? (out + (size_t)NN * FF + (size_t)l * EE * HH)
            : stage;
        edge_kernel<<<eblocks, 256>>>(hout_sel[l], out, alpha_out, (l < LL - 1) ? 1 : 0);
    }
}

// round 10
// speedup vs baseline: 1.6822x; 1.0752x over previous
#include <cuda_runtime.h>
#include <cuda_bf16.h>
#include <math.h>
#include <stdint.h>

#define NN 50000
#define EE 800000
#define FF 128
#define HH 8
#define LL 4

#define SCAN_B 256
#define SCAN_NB ((NN + SCAN_B - 1) / SCAN_B)   // 196
#define MTILES ((NN + 127) / 128)              // 391

// smem tile geometry: 128 rows x 128 bf16 cols, padded to 136 (272B rows)
#define SJ 136
#define TILE_BYTES (128 * SJ * 2)              // 34816
#define SMEM_TOTAL (4 * TILE_BYTES)            // 139264

// ---------------- scratch (static device allocations; no cudaMalloc) ----------------
__device__ float g_Q[NN * FF];
__device__ float g_K[NN * FF];
__device__ float g_V[NN * FF];
__device__ float g_S[NN * FF];
__device__ float g_alpha_stage[EE * HH];
__device__ __nv_bfloat16 g_X0[NN * FF];            // hi split of layer input
__device__ __nv_bfloat16 g_X1[NN * FF];            // lo split
__device__ __nv_bfloat16 g_B0[LL * 4 * FF * FF];   // W^T hi split, [l][which][n][k]
__device__ __nv_bfloat16 g_B1[LL * 4 * FF * FF];   // W^T lo split
__device__ int g_deg[NN];
__device__ int g_rowptr[NN + 1];
__device__ int g_cursor[NN];
__device__ int g_eidx[EE];
__device__ int g_srcs[EE];
__device__ int g_is64;
__device__ int g_blocksum[SCAN_NB];

// ---------------- dtype detection ----------------
__global__ void detect_kernel(const int* __restrict__ ei32) {
    int zeros = 0;
    for (int i = 0; i < 64; i++)
        if (ei32[2 * i + 1] == 0) zeros++;
    g_is64 = (zeros >= 48) ? 1 : 0;
}

__device__ __forceinline__ int load_idx(const void* eiv, long long pos) {
    if (g_is64) return (int)((const long long*)eiv)[pos];
    return ((const int*)eiv)[pos];
}

// ---------------- CSR construction ----------------
__global__ void zero_deg_kernel() {
    int i = blockIdx.x * blockDim.x + threadIdx.x;
    if (i < NN) g_deg[i] = 0;
}

__global__ void hist_kernel(const void* __restrict__ eiv) {
    int e = blockIdx.x * blockDim.x + threadIdx.x;
    if (e < EE) {
        int d = load_idx(eiv, (long long)EE + e);
        if (d >= 0 && d < NN) atomicAdd(&g_deg[d], 1);
    }
}

__global__ void __launch_bounds__(SCAN_B) reduce_kernel() {
    int tid = threadIdx.x, lane = tid & 31, wid = tid >> 5;
    int i = blockIdx.x * SCAN_B + tid;
    int v = (i < NN) ? g_deg[i] : 0;
#pragma unroll
    for (int o = 16; o > 0; o >>= 1) v += __shfl_down_sync(0xffffffffu, v, o);
    __shared__ int ws[8];
    if (lane == 0) ws[wid] = v;
    __syncthreads();
    if (tid == 0) {
        int s = 0;
#pragma unroll
        for (int w = 0; w < 8; w++) s += ws[w];
        g_blocksum[blockIdx.x] = s;
    }
}

__device__ __forceinline__ int block_incl_scan(int v, int tid) {
    int lane = tid & 31, wid = tid >> 5;
    int x = v;
#pragma unroll
    for (int o = 1; o < 32; o <<= 1) {
        int t = __shfl_up_sync(0xffffffffu, x, o);
        if (lane >= o) x += t;
    }
    __shared__ int wsum[8];
    if (lane == 31) wsum[wid] = x;
    __syncthreads();
    if (wid == 0) {
        int y = (lane < 8) ? wsum[lane] : 0;
#pragma unroll
        for (int o = 1; o < 8; o <<= 1) {
            int t = __shfl_up_sync(0xffffffffu, y, o);
            if (lane >= o) y += t;
        }
        if (lane < 8) wsum[lane] = y;
    }
    __syncthreads();
    return x + ((wid > 0) ? wsum[wid - 1] : 0);
}

__global__ void __launch_bounds__(SCAN_B) scanpart_kernel() {
    int tid = threadIdx.x;
    int v = (tid < SCAN_NB) ? g_blocksum[tid] : 0;
    int incl = block_incl_scan(v, tid);
    if (tid < SCAN_NB) g_blocksum[tid] = incl - v;
}

__global__ void __launch_bounds__(SCAN_B) scanfinal_kernel() {
    int tid = threadIdx.x;
    int i = blockIdx.x * SCAN_B + tid;
    int v = (i < NN) ? g_deg[i] : 0;
    int incl = block_incl_scan(v, tid);
    int off = g_blocksum[blockIdx.x];
    if (i < NN) {
        int e = off + incl - v;
        g_rowptr[i] = e;
        g_cursor[i] = e;
    }
    if (i == NN - 1) g_rowptr[NN] = off + incl;
}

__global__ void scatter_kernel(const void* __restrict__ eiv) {
    int e = blockIdx.x * blockDim.x + threadIdx.x;
    if (e < EE) {
        int s = load_idx(eiv, e);
        int d = load_idx(eiv, (long long)EE + e);
        if (d >= 0 && d < NN && s >= 0 && s < NN) {
            int p = atomicAdd(&g_cursor[d], 1);
            if (p >= 0 && p < EE) {
                g_eidx[p] = e;
                g_srcs[p] = s;
            }
        }
    }
}

// ---------------- split helpers (fp32 -> hi/lo bf16) ----------------
__device__ __forceinline__ void split_bf16(float v, __nv_bfloat16& hi, __nv_bfloat16& lo) {
    hi = __float2bfloat16_rn(v);
    lo = __float2bfloat16_rn(v - __bfloat162float(hi));
}

// initial split of x into g_X0/g_X1 (once per launch)
__global__ void __launch_bounds__(256) splitx_kernel(const float* __restrict__ X) {
    int i = blockIdx.x * blockDim.x + threadIdx.x;   // float4 index
    if (i < NN * FF / 4) {
        float4 v = ((const float4*)X)[i];
        __nv_bfloat16 h0, l0, h1, l1, h2, l2, h3, l3;
        split_bf16(v.x, h0, l0); split_bf16(v.y, h1, l1);
        split_bf16(v.z, h2, l2); split_bf16(v.w, h3, l3);
        ((__nv_bfloat162*)g_X0)[2 * i]     = __nv_bfloat162(h0, h1);
        ((__nv_bfloat162*)g_X0)[2 * i + 1] = __nv_bfloat162(h2, h3);
        ((__nv_bfloat162*)g_X1)[2 * i]     = __nv_bfloat162(l0, l1);
        ((__nv_bfloat162*)g_X1)[2 * i + 1] = __nv_bfloat162(l2, l3);
    }
}

// transpose + split ALL layers' weights: B[l][which][n][k] = W_which[l][k][n]
__global__ void __launch_bounds__(256) splitw_all_kernel(
    const float* __restrict__ Wq, const float* __restrict__ Wk,
    const float* __restrict__ Wv, const float* __restrict__ Ws)
{
    int idx = blockIdx.x * blockDim.x + threadIdx.x;   // l*65536 + which*16384 + k*128 + n
    if (idx < LL * 4 * FF * FF) {
        int l = idx >> 16;
        int which = (idx >> 14) & 3;
        int r = idx & 16383;
        int k = r >> 7, n = r & 127;
        const float* W = (which == 0) ? Wq : ((which == 1) ? Wk : ((which == 2) ? Wv : Ws));
        float v = W[(size_t)l * FF * FF + r];
        __nv_bfloat16 hi, lo;
        split_bf16(v, hi, lo);
        size_t base = ((size_t)(l * 4 + which)) << 14;
        g_B0[base + n * FF + k] = hi;
        g_B1[base + n * FF + k] = lo;
    }
}

// ---------------- bf16 mma.sync GEMM: O = X @ W + b via 3-product split ----------------
__device__ __forceinline__ void mma_bf16(float* c, const uint32_t* a, const uint32_t* b) {
    asm volatile(
        "mma.sync.aligned.m16n8k16.row.col.f32.bf16.bf16.f32 "
        "{%0,%1,%2,%3}, {%4,%5,%6,%7}, {%8,%9}, {%0,%1,%2,%3};"
        : "+f"(c[0]), "+f"(c[1]), "+f"(c[2]), "+f"(c[3])
        : "r"(a[0]), "r"(a[1]), "r"(a[2]), "r"(a[3]), "r"(b[0]), "r"(b[1]));
}

// grid (MTILES, 4), 256 threads, 139 KB dynamic smem, 1 CTA/SM.
__global__ void __launch_bounds__(256, 1) gemm_mma_kernel(
    int l,
    const float* __restrict__ b0, const float* __restrict__ b1,
    const float* __restrict__ b2, const float* __restrict__ b3)
{
    extern __shared__ char smem[];
    uint32_t* A0w = (uint32_t*)smem;                       // [row][word] stride 68 words
    uint32_t* A1w = (uint32_t*)(smem + TILE_BYTES);
    uint32_t* B0w = (uint32_t*)(smem + 2 * TILE_BYTES);
    uint32_t* B1w = (uint32_t*)(smem + 3 * TILE_BYTES);
    const int WS = SJ / 2;  // 68 words per row

    int tid = threadIdx.x;
    int wid = tid >> 5, lane = tid & 31;
    int which = blockIdx.y;
    int row0 = blockIdx.x * 128;
    const float* bias = (which == 0) ? b0 : ((which == 1) ? b1 : ((which == 2) ? b2 : b3));
    float* O = (which == 0) ? g_Q : ((which == 1) ? g_K : ((which == 2) ? g_V : g_S));

    {
        const uint4* xa0 = (const uint4*)g_X0;
        const uint4* xa1 = (const uint4*)g_X1;
        size_t wbase = ((size_t)(l * 4 + which)) << 14;
        const uint4* wb0 = (const uint4*)(g_B0 + wbase);
        const uint4* wb1 = (const uint4*)(g_B1 + wbase);
        const uint4 z4 = make_uint4(0u, 0u, 0u, 0u);
#pragma unroll
        for (int it = 0; it < 8; it++) {
            int i = tid + it * 256;          // 0..2047
            int row = i >> 4, c16 = i & 15;  // 16B chunk index in row
            int so = row * (SJ / 8) + c16;   // uint4 index with padding (SJ/8 = 17)
            bool ok = (row0 + row) < NN;
            size_t gi = ((size_t)(row0 + row) * FF) / 8 + c16;
            ((uint4*)A0w)[so] = ok ? xa0[gi] : z4;
            ((uint4*)A1w)[so] = ok ? xa1[gi] : z4;
            size_t bi = ((size_t)row * FF) / 8 + c16;
            ((uint4*)B0w)[so] = wb0[bi];
            ((uint4*)B1w)[so] = wb1[bi];
        }
    }
    __syncthreads();

    int wm = (wid >> 2) * 64;
    int wn = (wid & 3) * 32;
    int g = lane >> 2, tg = lane & 3;

    float c[4][4][4];
#pragma unroll
    for (int mt = 0; mt < 4; mt++)
#pragma unroll
        for (int nt = 0; nt < 4; nt++)
#pragma unroll
            for (int r = 0; r < 4; r++) c[mt][nt][r] = 0.f;

    int arow[4], brow[4];
#pragma unroll
    for (int mt = 0; mt < 4; mt++) arow[mt] = (wm + mt * 16 + g) * WS;
#pragma unroll
    for (int nt = 0; nt < 4; nt++) brow[nt] = (wn + nt * 8 + g) * WS;

#pragma unroll
    for (int ks = 0; ks < 8; ks++) {
        int kw = ks * 8 + tg;
        uint32_t ah[4][4], bh[4][2], al[4][4], bl[4][2];
#pragma unroll
        for (int mt = 0; mt < 4; mt++) {
            ah[mt][0] = A0w[arow[mt] + kw];
            ah[mt][1] = A0w[arow[mt] + 8 * WS + kw];
            ah[mt][2] = A0w[arow[mt] + kw + 4];
            ah[mt][3] = A0w[arow[mt] + 8 * WS + kw + 4];
        }
#pragma unroll
        for (int nt = 0; nt < 4; nt++) {
            bh[nt][0] = B0w[brow[nt] + kw];
            bh[nt][1] = B0w[brow[nt] + kw + 4];
        }
#pragma unroll
        for (int mt = 0; mt < 4; mt++)
#pragma unroll
            for (int nt = 0; nt < 4; nt++) mma_bf16(c[mt][nt], ah[mt], bh[nt]);

#pragma unroll
        for (int nt = 0; nt < 4; nt++) {
            bl[nt][0] = B1w[brow[nt] + kw];
            bl[nt][1] = B1w[brow[nt] + kw + 4];
        }
#pragma unroll
        for (int mt = 0; mt < 4; mt++)
#pragma unroll
            for (int nt = 0; nt < 4; nt++) mma_bf16(c[mt][nt], ah[mt], bl[nt]);

#pragma unroll
        for (int mt = 0; mt < 4; mt++) {
            al[mt][0] = A1w[arow[mt] + kw];
            al[mt][1] = A1w[arow[mt] + 8 * WS + kw];
            al[mt][2] = A1w[arow[mt] + kw + 4];
            al[mt][3] = A1w[arow[mt] + 8 * WS + kw + 4];
        }
#pragma unroll
        for (int mt = 0; mt < 4; mt++)
#pragma unroll
            for (int nt = 0; nt < 4; nt++) mma_bf16(c[mt][nt], al[mt], bh[nt]);
    }

#pragma unroll
    for (int mt = 0; mt < 4; mt++) {
#pragma unroll
        for (int nt = 0; nt < 4; nt++) {
            int col = wn + nt * 8 + tg * 2;
            float bx = bias[col], by = bias[col + 1];
            int row = row0 + wm + mt * 16 + g;
            if (row < NN) {
                float2* p = (float2*)(O + (size_t)row * FF + col);
                *p = make_float2(c[mt][nt][0] + bx, c[mt][nt][1] + by);
            }
            if (row + 8 < NN) {
                float2* p = (float2*)(O + (size_t)(row + 8) * FF + col);
                *p = make_float2(c[mt][nt][2] + bx, c[mt][nt][3] + by);
            }
        }
    }
}

// ---------------- edge phase v2: 3 chain-free passes, one warp per node ----------------
// pass1: K-dot -> raw alpha store + running max (fmax chain only)
// pass2: reload alpha (same-lane RAW + shfl broadcast), exp off-chain, denom/acc FFMA chains
// pass3: all-lane normalized rewrite (4 edges x 8 heads per iteration)
// epilogue: layers 0..2 write bf16 hi/lo splits (gelu applied); final layer writes fp32 out.
__global__ void __launch_bounds__(256) edge_kernel(
    int final_layer, float* __restrict__ out_h, float* __restrict__ alpha_out)
{
    int gw = (blockIdx.x * blockDim.x + threadIdx.x) >> 5;
    int lane = threadIdx.x & 31;
    if (gw >= NN) return;
    int n = gw;
    int beg = g_rowptr[n];
    int end = g_rowptr[n + 1];

    float4 q4 = ((const float4*)(g_Q + (size_t)n * FF))[lane];
    int h = lane >> 2;   // head id (4 lanes per head)

    // ---- pass 1: alphas + max ----
    float m = -3.0e38f;
#pragma unroll 2
    for (int p = beg; p < end; p++) {
        int s = g_srcs[p];
        float4 k4 = ((const float4*)(g_K + (size_t)s * FF))[lane];
        float d = q4.x * k4.x + q4.y * k4.y + q4.z * k4.z + q4.w * k4.w;
        d += __shfl_xor_sync(0xffffffffu, d, 1);
        d += __shfl_xor_sync(0xffffffffu, d, 2);
        float alpha = d * 0.25f;   // 1/sqrt(16)
        if ((lane & 3) == 0) alpha_out[(size_t)g_eidx[p] * HH + h] = alpha;
        m = fmaxf(m, alpha);
    }

    // ---- pass 2: denom + weighted V accumulation ----
    float denom = 0.f;
    float4 acc = make_float4(0.f, 0.f, 0.f, 0.f);
#pragma unroll 2
    for (int p = beg; p < end; p++) {
        int s = g_srcs[p];
        float a = 0.f;
        if ((lane & 3) == 0) a = alpha_out[(size_t)g_eidx[p] * HH + h];  // same-lane RAW
        a = __shfl_sync(0xffffffffu, a, lane & ~3);                       // broadcast in group
        float pe = __expf(a - m);   // independent across iterations (off-chain)
        float4 v4 = ((const float4*)(g_V + (size_t)s * FF))[lane];
        denom += pe;
        acc.x += pe * v4.x;
        acc.y += pe * v4.y;
        acc.z += pe * v4.z;
        acc.w += pe * v4.w;
    }

    float inv = (end > beg && denom > 0.f) ? 1.f / denom : 0.f;

    // ---- epilogue: node output ----
    float4 s4 = ((const float4*)(g_S + (size_t)n * FF))[lane];
    float4 o;
    o.x = acc.x * inv + s4.x;
    o.y = acc.y * inv + s4.y;
    o.z = acc.z * inv + s4.z;
    o.w = acc.w * inv + s4.w;
    if (!final_layer) {
        o.x = 0.5f * o.x * (1.f + erff(o.x * 0.70710678118654752f));
        o.y = 0.5f * o.y * (1.f + erff(o.y * 0.70710678118654752f));
        o.z = 0.5f * o.z * (1.f + erff(o.z * 0.70710678118654752f));
        o.w = 0.5f * o.w * (1.f + erff(o.w * 0.70710678118654752f));
        // write bf16 hi/lo splits directly (next layer's GEMM input)
        __nv_bfloat16 h0, l0, h1, l1, h2, l2, h3, l3;
        split_bf16(o.x, h0, l0); split_bf16(o.y, h1, l1);
        split_bf16(o.z, h2, l2); split_bf16(o.w, h3, l3);
        __nv_bfloat162* p0 = (__nv_bfloat162*)(g_X0 + (size_t)n * FF);
        __nv_bfloat162* p1 = (__nv_bfloat162*)(g_X1 + (size_t)n * FF);
        p0[lane * 2]     = __nv_bfloat162(h0, h1);
        p0[lane * 2 + 1] = __nv_bfloat162(h2, h3);
        p1[lane * 2]     = __nv_bfloat162(l0, l1);
        p1[lane * 2 + 1] = __nv_bfloat162(l2, l3);
    } else {
        ((float4*)(out_h + (size_t)n * FF))[lane] = o;
    }

    // ---- pass 3: normalized alpha rewrite, 4 edges per iteration ----
    __syncwarp();   // order pass-1 stores vs cross-lane reads below
    int h2 = lane & 7;
    float mh  = __shfl_sync(0xffffffffu, m,   h2 * 4);
    float invh = __shfl_sync(0xffffffffu, inv, h2 * 4);
    for (int p0i = beg; p0i < end; p0i += 4) {
        int p = p0i + (lane >> 3);
        if (p < end) {
            size_t eo = (size_t)g_eidx[p] * HH + h2;
            float a = alpha_out[eo];
            alpha_out[eo] = __expf(a - mh) * invh;
        }
    }
}

static float* alpha_stage_ptr() {
    void* p = nullptr;
    cudaGetSymbolAddress(&p, g_alpha_stage);
    return (float*)p;
}

// ---------------- launch ----------------
extern "C" void kernel_launch(void* const* d_in, const int* in_sizes, int n_in,
                              void* d_out, int out_size)
{
    const float* x = (const float*)d_in[0];
    const void* ei = (const void*)d_in[1];
    const float* Wq = (const float*)d_in[2];
    const float* bq = (const float*)d_in[3];
    const float* Wk = (const float*)d_in[4];
    const float* bk = (const float*)d_in[5];
    const float* Wv = (const float*)d_in[6];
    const float* bv = (const float*)d_in[7];
    const float* Ws = (const float*)d_in[8];
    const float* bs = (const float*)d_in[9];
    float* out = (float*)d_out;

    cudaFuncSetAttribute(gemm_mma_kernel, cudaFuncAttributeMaxDynamicSharedMemorySize, SMEM_TOTAL);

    const long long full_elems = (long long)NN * FF + (long long)LL * EE * HH;
    bool alphas_in_out = ((long long)out_size >= full_elems);
    float* stage = alphas_in_out ? nullptr : alpha_stage_ptr();

    detect_kernel<<<1, 1>>>((const int*)ei);
    zero_deg_kernel<<<(NN + 255) / 256, 256>>>();
    hist_kernel<<<(EE + 255) / 256, 256>>>(ei);
    reduce_kernel<<<SCAN_NB, SCAN_B>>>();
    scanpart_kernel<<<1, SCAN_B>>>();
    scanfinal_kernel<<<SCAN_NB, SCAN_B>>>();
    scatter_kernel<<<(EE + 255) / 256, 256>>>(ei);

    // all-layer weight split (1 launch) + initial x split
    splitw_all_kernel<<<(LL * 4 * FF * FF + 255) / 256, 256>>>(Wq, Wk, Wv, Ws);
    splitx_kernel<<<(NN * FF / 4 + 255) / 256, 256>>>(x);

    dim3 ggrid(MTILES, 4);
    int eblocks = (NN * 32 + 255) / 256;

    for (int l = 0; l < LL; l++) {
        size_t bofs = (size_t)l * FF;
        gemm_mma_kernel<<<ggrid, 256, SMEM_TOTAL>>>(l, bq + bofs, bk + bofs, bv + bofs, bs + bofs);
        float* alpha_out = alphas_in_out
            ? (out + (size_t)NN * FF + (size_t)l * EE * HH)
            : stage;
        edge_kernel<<<eblocks, 256>>>((l == LL - 1) ? 1 : 0, out, alpha_out);
    }
}

// round 11
// speedup vs baseline: 1.7086x; 1.0157x over previous
#include <cuda_runtime.h>
#include <cuda_bf16.h>
#include <math.h>
#include <stdint.h>

#define NN 50000
#define EE 800000
#define FF 128
#define HH 8
#define LL 4

#define SCAN_B 256
#define SCAN_NB ((NN + SCAN_B - 1) / SCAN_B)   // 196
#define MTILES ((NN + 127) / 128)              // 391

// smem tile geometry: 128 rows x 64 bf16 cols (BK=64), padded to 72 (144B rows)
#define SJ2 72
#define WS2 (SJ2 / 2)                          // 36 words per row
#define TILE2_BYTES (128 * SJ2 * 2)            // 18432
#define SMEM2_TOTAL (4 * TILE2_BYTES)          // 73728

// ---------------- scratch (static device allocations; no cudaMalloc) ----------------
__device__ float g_Q[NN * FF];
__device__ float g_K[NN * FF];
__device__ float g_V[NN * FF];
__device__ float g_S[NN * FF];
__device__ float g_alpha_stage[EE * HH];
__device__ __nv_bfloat16 g_X0[NN * FF];            // hi split of layer input
__device__ __nv_bfloat16 g_X1[NN * FF];            // lo split
__device__ __nv_bfloat16 g_B0[LL * 4 * FF * FF];   // W^T hi split, [l][which][n][k]
__device__ __nv_bfloat16 g_B1[LL * 4 * FF * FF];   // W^T lo split
__device__ int g_deg[NN];
__device__ int g_rowptr[NN + 1];
__device__ int g_cursor[NN];
__device__ int g_eidx[EE];
__device__ int g_srcs[EE];
__device__ int g_is64;
__device__ int g_blocksum[SCAN_NB];

// ---------------- dtype detection ----------------
__global__ void detect_kernel(const int* __restrict__ ei32) {
    int zeros = 0;
    for (int i = 0; i < 64; i++)
        if (ei32[2 * i + 1] == 0) zeros++;
    g_is64 = (zeros >= 48) ? 1 : 0;
}

__device__ __forceinline__ int load_idx(const void* eiv, long long pos) {
    if (g_is64) return (int)((const long long*)eiv)[pos];
    return ((const int*)eiv)[pos];
}

// ---------------- CSR construction ----------------
__global__ void zero_deg_kernel() {
    int i = blockIdx.x * blockDim.x + threadIdx.x;
    if (i < NN) g_deg[i] = 0;
}

__global__ void hist_kernel(const void* __restrict__ eiv) {
    int e = blockIdx.x * blockDim.x + threadIdx.x;
    if (e < EE) {
        int d = load_idx(eiv, (long long)EE + e);
        if (d >= 0 && d < NN) atomicAdd(&g_deg[d], 1);
    }
}

__global__ void __launch_bounds__(SCAN_B) reduce_kernel() {
    int tid = threadIdx.x, lane = tid & 31, wid = tid >> 5;
    int i = blockIdx.x * SCAN_B + tid;
    int v = (i < NN) ? g_deg[i] : 0;
#pragma unroll
    for (int o = 16; o > 0; o >>= 1) v += __shfl_down_sync(0xffffffffu, v, o);
    __shared__ int ws[8];
    if (lane == 0) ws[wid] = v;
    __syncthreads();
    if (tid == 0) {
        int s = 0;
#pragma unroll
        for (int w = 0; w < 8; w++) s += ws[w];
        g_blocksum[blockIdx.x] = s;
    }
}

__device__ __forceinline__ int block_incl_scan(int v, int tid) {
    int lane = tid & 31, wid = tid >> 5;
    int x = v;
#pragma unroll
    for (int o = 1; o < 32; o <<= 1) {
        int t = __shfl_up_sync(0xffffffffu, x, o);
        if (lane >= o) x += t;
    }
    __shared__ int wsum[8];
    if (lane == 31) wsum[wid] = x;
    __syncthreads();
    if (wid == 0) {
        int y = (lane < 8) ? wsum[lane] : 0;
#pragma unroll
        for (int o = 1; o < 8; o <<= 1) {
            int t = __shfl_up_sync(0xffffffffu, y, o);
            if (lane >= o) y += t;
        }
        if (lane < 8) wsum[lane] = y;
    }
    __syncthreads();
    return x + ((wid > 0) ? wsum[wid - 1] : 0);
}

__global__ void __launch_bounds__(SCAN_B) scanpart_kernel() {
    int tid = threadIdx.x;
    int v = (tid < SCAN_NB) ? g_blocksum[tid] : 0;
    int incl = block_incl_scan(v, tid);
    if (tid < SCAN_NB) g_blocksum[tid] = incl - v;
}

__global__ void __launch_bounds__(SCAN_B) scanfinal_kernel() {
    int tid = threadIdx.x;
    int i = blockIdx.x * SCAN_B + tid;
    int v = (i < NN) ? g_deg[i] : 0;
    int incl = block_incl_scan(v, tid);
    int off = g_blocksum[blockIdx.x];
    if (i < NN) {
        int e = off + incl - v;
        g_rowptr[i] = e;
        g_cursor[i] = e;
    }
    if (i == NN - 1) g_rowptr[NN] = off + incl;
}

__global__ void scatter_kernel(const void* __restrict__ eiv) {
    int e = blockIdx.x * blockDim.x + threadIdx.x;
    if (e < EE) {
        int s = load_idx(eiv, e);
        int d = load_idx(eiv, (long long)EE + e);
        if (d >= 0 && d < NN && s >= 0 && s < NN) {
            int p = atomicAdd(&g_cursor[d], 1);
            if (p >= 0 && p < EE) {
                g_eidx[p] = e;
                g_srcs[p] = s;
            }
        }
    }
}

// ---------------- split helpers (fp32 -> hi/lo bf16) ----------------
__device__ __forceinline__ void split_bf16(float v, __nv_bfloat16& hi, __nv_bfloat16& lo) {
    hi = __float2bfloat16_rn(v);
    lo = __float2bfloat16_rn(v - __bfloat162float(hi));
}

__global__ void __launch_bounds__(256) splitx_kernel(const float* __restrict__ X) {
    int i = blockIdx.x * blockDim.x + threadIdx.x;   // float4 index
    if (i < NN * FF / 4) {
        float4 v = ((const float4*)X)[i];
        __nv_bfloat16 h0, l0, h1, l1, h2, l2, h3, l3;
        split_bf16(v.x, h0, l0); split_bf16(v.y, h1, l1);
        split_bf16(v.z, h2, l2); split_bf16(v.w, h3, l3);
        ((__nv_bfloat162*)g_X0)[2 * i]     = __nv_bfloat162(h0, h1);
        ((__nv_bfloat162*)g_X0)[2 * i + 1] = __nv_bfloat162(h2, h3);
        ((__nv_bfloat162*)g_X1)[2 * i]     = __nv_bfloat162(l0, l1);
        ((__nv_bfloat162*)g_X1)[2 * i + 1] = __nv_bfloat162(l2, l3);
    }
}

__global__ void __launch_bounds__(256) splitw_all_kernel(
    const float* __restrict__ Wq, const float* __restrict__ Wk,
    const float* __restrict__ Wv, const float* __restrict__ Ws)
{
    int idx = blockIdx.x * blockDim.x + threadIdx.x;   // l*65536 + which*16384 + k*128 + n
    if (idx < LL * 4 * FF * FF) {
        int l = idx >> 16;
        int which = (idx >> 14) & 3;
        int r = idx & 16383;
        int k = r >> 7, n = r & 127;
        const float* W = (which == 0) ? Wq : ((which == 1) ? Wk : ((which == 2) ? Wv : Ws));
        float v = W[(size_t)l * FF * FF + r];
        __nv_bfloat16 hi, lo;
        split_bf16(v, hi, lo);
        size_t base = ((size_t)(l * 4 + which)) << 14;
        g_B0[base + n * FF + k] = hi;
        g_B1[base + n * FF + k] = lo;
    }
}

// ---------------- bf16 mma.sync GEMM: O = X @ W + b via 3-product split ----------------
__device__ __forceinline__ void mma_bf16(float* c, const uint32_t* a, const uint32_t* b) {
    asm volatile(
        "mma.sync.aligned.m16n8k16.row.col.f32.bf16.bf16.f32 "
        "{%0,%1,%2,%3}, {%4,%5,%6,%7}, {%8,%9}, {%0,%1,%2,%3};"
        : "+f"(c[0]), "+f"(c[1]), "+f"(c[2]), "+f"(c[3])
        : "r"(a[0]), "r"(a[1]), "r"(a[2]), "r"(a[3]), "r"(b[0]), "r"(b[1]));
}

// grid (MTILES, 4), 256 threads, BK=64 x 2 steps, 73.7 KB smem -> 2 CTAs/SM.
__global__ void __launch_bounds__(256, 2) gemm_mma_kernel(
    int l,
    const float* __restrict__ b0, const float* __restrict__ b1,
    const float* __restrict__ b2, const float* __restrict__ b3)
{
    extern __shared__ char smem[];
    uint32_t* A0w = (uint32_t*)smem;
    uint32_t* A1w = (uint32_t*)(smem + TILE2_BYTES);
    uint32_t* B0w = (uint32_t*)(smem + 2 * TILE2_BYTES);
    uint32_t* B1w = (uint32_t*)(smem + 3 * TILE2_BYTES);

    int tid = threadIdx.x;
    int wid = tid >> 5, lane = tid & 31;
    int which = blockIdx.y;
    int row0 = blockIdx.x * 128;
    const float* bias = (which == 0) ? b0 : ((which == 1) ? b1 : ((which == 2) ? b2 : b3));
    float* O = (which == 0) ? g_Q : ((which == 1) ? g_K : ((which == 2) ? g_V : g_S));

    int wm = (wid >> 2) * 64;
    int wn = (wid & 3) * 32;
    int g = lane >> 2, tg = lane & 3;

    float c[4][4][4];
#pragma unroll
    for (int mt = 0; mt < 4; mt++)
#pragma unroll
        for (int nt = 0; nt < 4; nt++)
#pragma unroll
            for (int r = 0; r < 4; r++) c[mt][nt][r] = 0.f;

    int arow[4], brow[4];
#pragma unroll
    for (int mt = 0; mt < 4; mt++) arow[mt] = (wm + mt * 16 + g) * WS2;
#pragma unroll
    for (int nt = 0; nt < 4; nt++) brow[nt] = (wn + nt * 8 + g) * WS2;

    const uint4* xa0 = (const uint4*)g_X0;
    const uint4* xa1 = (const uint4*)g_X1;
    size_t wbase = ((size_t)(l * 4 + which)) << 14;
    const uint4* wb0 = (const uint4*)(g_B0 + wbase);
    const uint4* wb1 = (const uint4*)(g_B1 + wbase);
    const uint4 z4 = make_uint4(0u, 0u, 0u, 0u);

#pragma unroll
    for (int kc = 0; kc < 2; kc++) {
        // stage 128x64 tiles: 1024 uint4 per tile, 4 per thread per tile
#pragma unroll
        for (int it = 0; it < 4; it++) {
            int i = tid + it * 256;          // 0..1023
            int row = i >> 3, c8 = i & 7;    // 8 uint4 chunks per row
            int so = row * (WS2 / 4) + c8;   // uint4 index (9 per padded row)
            bool ok = (row0 + row) < NN;
            size_t gi = (size_t)(row0 + row) * 16 + kc * 8 + c8;
            ((uint4*)A0w)[so] = ok ? xa0[gi] : z4;
            ((uint4*)A1w)[so] = ok ? xa1[gi] : z4;
            size_t bi = (size_t)row * 16 + kc * 8 + c8;
            ((uint4*)B0w)[so] = wb0[bi];
            ((uint4*)B1w)[so] = wb1[bi];
        }
        __syncthreads();

#pragma unroll
        for (int ks = 0; ks < 4; ks++) {
            int kw = ks * 8 + tg;
            uint32_t ah[4][4], bh[4][2], al[4][4], bl[4][2];
#pragma unroll
            for (int mt = 0; mt < 4; mt++) {
                ah[mt][0] = A0w[arow[mt] + kw];
                ah[mt][1] = A0w[arow[mt] + 8 * WS2 + kw];
                ah[mt][2] = A0w[arow[mt] + kw + 4];
                ah[mt][3] = A0w[arow[mt] + 8 * WS2 + kw + 4];
            }
#pragma unroll
            for (int nt = 0; nt < 4; nt++) {
                bh[nt][0] = B0w[brow[nt] + kw];
                bh[nt][1] = B0w[brow[nt] + kw + 4];
            }
#pragma unroll
            for (int mt = 0; mt < 4; mt++)
#pragma unroll
                for (int nt = 0; nt < 4; nt++) mma_bf16(c[mt][nt], ah[mt], bh[nt]);

#pragma unroll
            for (int nt = 0; nt < 4; nt++) {
                bl[nt][0] = B1w[brow[nt] + kw];
                bl[nt][1] = B1w[brow[nt] + kw + 4];
            }
#pragma unroll
            for (int mt = 0; mt < 4; mt++)
#pragma unroll
                for (int nt = 0; nt < 4; nt++) mma_bf16(c[mt][nt], ah[mt], bl[nt]);

#pragma unroll
            for (int mt = 0; mt < 4; mt++) {
                al[mt][0] = A1w[arow[mt] + kw];
                al[mt][1] = A1w[arow[mt] + 8 * WS2 + kw];
                al[mt][2] = A1w[arow[mt] + kw + 4];
                al[mt][3] = A1w[arow[mt] + 8 * WS2 + kw + 4];
            }
#pragma unroll
            for (int mt = 0; mt < 4; mt++)
#pragma unroll
                for (int nt = 0; nt < 4; nt++) mma_bf16(c[mt][nt], al[mt], bh[nt]);
        }
        __syncthreads();
    }

#pragma unroll
    for (int mt = 0; mt < 4; mt++) {
#pragma unroll
        for (int nt = 0; nt < 4; nt++) {
            int col = wn + nt * 8 + tg * 2;
            float bx = bias[col], by = bias[col + 1];
            int row = row0 + wm + mt * 16 + g;
            if (row < NN) {
                float2* p = (float2*)(O + (size_t)row * FF + col);
                *p = make_float2(c[mt][nt][0] + bx, c[mt][nt][1] + by);
            }
            if (row + 8 < NN) {
                float2* p = (float2*)(O + (size_t)(row + 8) * FF + col);
                *p = make_float2(c[mt][nt][2] + bx, c[mt][nt][3] + by);
            }
        }
    }
}

// ---------------- edge phase: 3 chain-free passes, one warp per node ----------------
// pass1: K-dot -> raw alpha store + running max
// pass2: reload alpha, exp off-chain, denom/acc; leader lane overwrites alpha with pe
// pass3: pure scale pe * inv (no exp), 4 edges x 8 heads per iteration
__global__ void __launch_bounds__(256) edge_kernel(
    int final_layer, float* __restrict__ out_h, float* __restrict__ alpha_out)
{
    int gw = (blockIdx.x * blockDim.x + threadIdx.x) >> 5;
    int lane = threadIdx.x & 31;
    if (gw >= NN) return;
    int n = gw;
    int beg = g_rowptr[n];
    int end = g_rowptr[n + 1];

    float4 q4 = ((const float4*)(g_Q + (size_t)n * FF))[lane];
    int h = lane >> 2;

    // ---- pass 1: alphas + max ----
    float m = -3.0e38f;
#pragma unroll 2
    for (int p = beg; p < end; p++) {
        int s = g_srcs[p];
        float4 k4 = ((const float4*)(g_K + (size_t)s * FF))[lane];
        float d = q4.x * k4.x + q4.y * k4.y + q4.z * k4.z + q4.w * k4.w;
        d += __shfl_xor_sync(0xffffffffu, d, 1);
        d += __shfl_xor_sync(0xffffffffu, d, 2);
        float alpha = d * 0.25f;
        if ((lane & 3) == 0) alpha_out[(size_t)g_eidx[p] * HH + h] = alpha;
        m = fmaxf(m, alpha);
    }

    // ---- pass 2: denom + weighted V accumulation; store pe over raw alpha ----
    float denom = 0.f;
    float4 acc = make_float4(0.f, 0.f, 0.f, 0.f);
#pragma unroll 2
    for (int p = beg; p < end; p++) {
        int s = g_srcs[p];
        size_t eo = (size_t)g_eidx[p] * HH + h;
        float a = 0.f;
        if ((lane & 3) == 0) a = alpha_out[eo];          // same-lane RAW
        a = __shfl_sync(0xffffffffu, a, lane & ~3);      // broadcast in group
        float pe = __expf(a - m);
        if ((lane & 3) == 0) alpha_out[eo] = pe;         // pass3 reads pe, no 2nd exp
        float4 v4 = ((const float4*)(g_V + (size_t)s * FF))[lane];
        denom += pe;
        acc.x += pe * v4.x;
        acc.y += pe * v4.y;
        acc.z += pe * v4.z;
        acc.w += pe * v4.w;
    }

    float inv = (end > beg && denom > 0.f) ? 1.f / denom : 0.f;

    // ---- epilogue: node output ----
    float4 s4 = ((const float4*)(g_S + (size_t)n * FF))[lane];
    float4 o;
    o.x = acc.x * inv + s4.x;
    o.y = acc.y * inv + s4.y;
    o.z = acc.z * inv + s4.z;
    o.w = acc.w * inv + s4.w;
    if (!final_layer) {
        o.x = 0.5f * o.x * (1.f + erff(o.x * 0.70710678118654752f));
        o.y = 0.5f * o.y * (1.f + erff(o.y * 0.70710678118654752f));
        o.z = 0.5f * o.z * (1.f + erff(o.z * 0.70710678118654752f));
        o.w = 0.5f * o.w * (1.f + erff(o.w * 0.70710678118654752f));
        __nv_bfloat16 h0, l0, h1, l1, h2c, l2, h3, l3;
        split_bf16(o.x, h0, l0); split_bf16(o.y, h1, l1);
        split_bf16(o.z, h2c, l2); split_bf16(o.w, h3, l3);
        __nv_bfloat162* p0 = (__nv_bfloat162*)(g_X0 + (size_t)n * FF);
        __nv_bfloat162* p1 = (__nv_bfloat162*)(g_X1 + (size_t)n * FF);
        p0[lane * 2]     = __nv_bfloat162(h0, h1);
        p0[lane * 2 + 1] = __nv_bfloat162(h2c, h3);
        p1[lane * 2]     = __nv_bfloat162(l0, l1);
        p1[lane * 2 + 1] = __nv_bfloat162(l2, l3);
    } else {
        ((float4*)(out_h + (size_t)n * FF))[lane] = o;
    }

    // ---- pass 3: scale pe by inv, 4 edges per iteration ----
    __syncwarp();   // order pass-2 pe stores vs cross-lane reads below
    int h2 = lane & 7;
    float invh = __shfl_sync(0xffffffffu, inv, h2 * 4);
    for (int p0i = beg; p0i < end; p0i += 4) {
        int p = p0i + (lane >> 3);
        if (p < end) {
            size_t eo = (size_t)g_eidx[p] * HH + h2;
            alpha_out[eo] *= invh;
        }
    }
}

static float* alpha_stage_ptr() {
    void* p = nullptr;
    cudaGetSymbolAddress(&p, g_alpha_stage);
    return (float*)p;
}

// ---------------- launch ----------------
extern "C" void kernel_launch(void* const* d_in, const int* in_sizes, int n_in,
                              void* d_out, int out_size)
{
    const float* x = (const float*)d_in[0];
    const void* ei = (const void*)d_in[1];
    const float* Wq = (const float*)d_in[2];
    const float* bq = (const float*)d_in[3];
    const float* Wk = (const float*)d_in[4];
    const float* bk = (const float*)d_in[5];
    const float* Wv = (const float*)d_in[6];
    const float* bv = (const float*)d_in[7];
    const float* Ws = (const float*)d_in[8];
    const float* bs = (const float*)d_in[9];
    float* out = (float*)d_out;

    cudaFuncSetAttribute(gemm_mma_kernel, cudaFuncAttributeMaxDynamicSharedMemorySize, SMEM2_TOTAL);

    const long long full_elems = (long long)NN * FF + (long long)LL * EE * HH;
    bool alphas_in_out = ((long long)out_size >= full_elems);
    float* stage = alphas_in_out ? nullptr : alpha_stage_ptr();

    detect_kernel<<<1, 1>>>((const int*)ei);
    zero_deg_kernel<<<(NN + 255) / 256, 256>>>();
    hist_kernel<<<(EE + 255) / 256, 256>>>(ei);
    reduce_kernel<<<SCAN_NB, SCAN_B>>>();
    scanpart_kernel<<<1, SCAN_B>>>();
    scanfinal_kernel<<<SCAN_NB, SCAN_B>>>();
    scatter_kernel<<<(EE + 255) / 256, 256>>>(ei);

    splitw_all_kernel<<<(LL * 4 * FF * FF + 255) / 256, 256>>>(Wq, Wk, Wv, Ws);
    splitx_kernel<<<(NN * FF / 4 + 255) / 256, 256>>>(x);

    dim3 ggrid(MTILES, 4);
    int eblocks = (NN * 32 + 255) / 256;

    for (int l = 0; l < LL; l++) {
        size_t bofs = (size_t)l * FF;
        gemm_mma_kernel<<<ggrid, 256, SMEM2_TOTAL>>>(l, bq + bofs, bk + bofs, bv + bofs, bs + bofs);
        float* alpha_out = alphas_in_out
            ? (out + (size_t)NN * FF + (size_t)l * EE * HH)
            : stage;
        edge_kernel<<<eblocks, 256>>>((l == LL - 1) ? 1 : 0, out, alpha_out);
    }
}

// round 12
// speedup vs baseline: 1.9872x; 1.1631x over previous
#include <cuda_runtime.h>
#include <cuda_bf16.h>
#include <math.h>
#include <stdint.h>

#define NN 50000
#define EE 800000
#define FF 128
#define HH 8
#define LL 4

#define SCAN_B 256
#define SCAN_NB ((NN + SCAN_B - 1) / SCAN_B)   // 196
#define MTILES ((NN + 127) / 128)              // 391

// smem tile geometry: 128 rows x 64 bf16 cols (BK=64), padded to 72 (144B rows)
#define SJ2 72
#define WS2 (SJ2 / 2)                          // 36 words per row
#define TILE2_BYTES (128 * SJ2 * 2)            // 18432
#define SMEM2_TOTAL (4 * TILE2_BYTES)          // 73728

// ---------------- scratch (static device allocations; no cudaMalloc) ----------------
__device__ float g_Q[NN * FF];
__device__ float g_K[NN * FF];
__device__ float g_V[NN * FF];
__device__ float g_S[NN * FF];
__device__ float g_stage[EE * HH];                 // CSR-ordered alpha staging (L2-hot)
__device__ float g_alpha_stage[EE * HH];           // fallback final sink if out buffer lacks room
__device__ __nv_bfloat16 g_X0[NN * FF];            // hi split of layer input
__device__ __nv_bfloat16 g_X1[NN * FF];            // lo split
__device__ __nv_bfloat16 g_B0[LL * 4 * FF * FF];   // W^T hi split, [l][which][n][k]
__device__ __nv_bfloat16 g_B1[LL * 4 * FF * FF];   // W^T lo split
__device__ int g_deg[NN];
__device__ int g_rowptr[NN + 1];
__device__ int g_cursor[NN];
__device__ int g_eidx[EE];
__device__ int g_srcs[EE];
__device__ int g_is64;
__device__ int g_blocksum[SCAN_NB];

// ---------------- dtype detection ----------------
__global__ void detect_kernel(const int* __restrict__ ei32) {
    int zeros = 0;
    for (int i = 0; i < 64; i++)
        if (ei32[2 * i + 1] == 0) zeros++;
    g_is64 = (zeros >= 48) ? 1 : 0;
}

__device__ __forceinline__ int load_idx(const void* eiv, long long pos) {
    if (g_is64) return (int)((const long long*)eiv)[pos];
    return ((const int*)eiv)[pos];
}

// ---------------- CSR construction ----------------
__global__ void zero_deg_kernel() {
    int i = blockIdx.x * blockDim.x + threadIdx.x;
    if (i < NN) g_deg[i] = 0;
}

__global__ void hist_kernel(const void* __restrict__ eiv) {
    int e = blockIdx.x * blockDim.x + threadIdx.x;
    if (e < EE) {
        int d = load_idx(eiv, (long long)EE + e);
        if (d >= 0 && d < NN) atomicAdd(&g_deg[d], 1);
    }
}

__global__ void __launch_bounds__(SCAN_B) reduce_kernel() {
    int tid = threadIdx.x, lane = tid & 31, wid = tid >> 5;
    int i = blockIdx.x * SCAN_B + tid;
    int v = (i < NN) ? g_deg[i] : 0;
#pragma unroll
    for (int o = 16; o > 0; o >>= 1) v += __shfl_down_sync(0xffffffffu, v, o);
    __shared__ int ws[8];
    if (lane == 0) ws[wid] = v;
    __syncthreads();
    if (tid == 0) {
        int s = 0;
#pragma unroll
        for (int w = 0; w < 8; w++) s += ws[w];
        g_blocksum[blockIdx.x] = s;
    }
}

__device__ __forceinline__ int block_incl_scan(int v, int tid) {
    int lane = tid & 31, wid = tid >> 5;
    int x = v;
#pragma unroll
    for (int o = 1; o < 32; o <<= 1) {
        int t = __shfl_up_sync(0xffffffffu, x, o);
        if (lane >= o) x += t;
    }
    __shared__ int wsum[8];
    if (lane == 31) wsum[wid] = x;
    __syncthreads();
    if (wid == 0) {
        int y = (lane < 8) ? wsum[lane] : 0;
#pragma unroll
        for (int o = 1; o < 8; o <<= 1) {
            int t = __shfl_up_sync(0xffffffffu, y, o);
            if (lane >= o) y += t;
        }
        if (lane < 8) wsum[lane] = y;
    }
    __syncthreads();
    return x + ((wid > 0) ? wsum[wid - 1] : 0);
}

__global__ void __launch_bounds__(SCAN_B) scanpart_kernel() {
    int tid = threadIdx.x;
    int v = (tid < SCAN_NB) ? g_blocksum[tid] : 0;
    int incl = block_incl_scan(v, tid);
    if (tid < SCAN_NB) g_blocksum[tid] = incl - v;
}

__global__ void __launch_bounds__(SCAN_B) scanfinal_kernel() {
    int tid = threadIdx.x;
    int i = blockIdx.x * SCAN_B + tid;
    int v = (i < NN) ? g_deg[i] : 0;
    int incl = block_incl_scan(v, tid);
    int off = g_blocksum[blockIdx.x];
    if (i < NN) {
        int e = off + incl - v;
        g_rowptr[i] = e;
        g_cursor[i] = e;
    }
    if (i == NN - 1) g_rowptr[NN] = off + incl;
}

__global__ void scatter_kernel(const void* __restrict__ eiv) {
    int e = blockIdx.x * blockDim.x + threadIdx.x;
    if (e < EE) {
        int s = load_idx(eiv, e);
        int d = load_idx(eiv, (long long)EE + e);
        if (d >= 0 && d < NN && s >= 0 && s < NN) {
            int p = atomicAdd(&g_cursor[d], 1);
            if (p >= 0 && p < EE) {
                g_eidx[p] = e;
                g_srcs[p] = s;
            }
        }
    }
}

// ---------------- split helpers (fp32 -> hi/lo bf16) ----------------
__device__ __forceinline__ void split_bf16(float v, __nv_bfloat16& hi, __nv_bfloat16& lo) {
    hi = __float2bfloat16_rn(v);
    lo = __float2bfloat16_rn(v - __bfloat162float(hi));
}

__global__ void __launch_bounds__(256) splitx_kernel(const float* __restrict__ X) {
    int i = blockIdx.x * blockDim.x + threadIdx.x;   // float4 index
    if (i < NN * FF / 4) {
        float4 v = ((const float4*)X)[i];
        __nv_bfloat16 h0, l0, h1, l1, h2, l2, h3, l3;
        split_bf16(v.x, h0, l0); split_bf16(v.y, h1, l1);
        split_bf16(v.z, h2, l2); split_bf16(v.w, h3, l3);
        ((__nv_bfloat162*)g_X0)[2 * i]     = __nv_bfloat162(h0, h1);
        ((__nv_bfloat162*)g_X0)[2 * i + 1] = __nv_bfloat162(h2, h3);
        ((__nv_bfloat162*)g_X1)[2 * i]     = __nv_bfloat162(l0, l1);
        ((__nv_bfloat162*)g_X1)[2 * i + 1] = __nv_bfloat162(l2, l3);
    }
}

__global__ void __launch_bounds__(256) splitw_all_kernel(
    const float* __restrict__ Wq, const float* __restrict__ Wk,
    const float* __restrict__ Wv, const float* __restrict__ Ws)
{
    int idx = blockIdx.x * blockDim.x + threadIdx.x;   // l*65536 + which*16384 + k*128 + n
    if (idx < LL * 4 * FF * FF) {
        int l = idx >> 16;
        int which = (idx >> 14) & 3;
        int r = idx & 16383;
        int k = r >> 7, n = r & 127;
        const float* W = (which == 0) ? Wq : ((which == 1) ? Wk : ((which == 2) ? Wv : Ws));
        float v = W[(size_t)l * FF * FF + r];
        __nv_bfloat16 hi, lo;
        split_bf16(v, hi, lo);
        size_t base = ((size_t)(l * 4 + which)) << 14;
        g_B0[base + n * FF + k] = hi;
        g_B1[base + n * FF + k] = lo;
    }
}

// ---------------- bf16 mma.sync GEMM: O = X @ W + b via 3-product split ----------------
__device__ __forceinline__ void mma_bf16(float* c, const uint32_t* a, const uint32_t* b) {
    asm volatile(
        "mma.sync.aligned.m16n8k16.row.col.f32.bf16.bf16.f32 "
        "{%0,%1,%2,%3}, {%4,%5,%6,%7}, {%8,%9}, {%0,%1,%2,%3};"
        : "+f"(c[0]), "+f"(c[1]), "+f"(c[2]), "+f"(c[3])
        : "r"(a[0]), "r"(a[1]), "r"(a[2]), "r"(a[3]), "r"(b[0]), "r"(b[1]));
}

// grid (MTILES, 4), 256 threads, BK=64 x 2 steps, 73.7 KB smem -> 2 CTAs/SM.
__global__ void __launch_bounds__(256, 2) gemm_mma_kernel(
    int l,
    const float* __restrict__ b0, const float* __restrict__ b1,
    const float* __restrict__ b2, const float* __restrict__ b3)
{
    extern __shared__ char smem[];
    uint32_t* A0w = (uint32_t*)smem;
    uint32_t* A1w = (uint32_t*)(smem + TILE2_BYTES);
    uint32_t* B0w = (uint32_t*)(smem + 2 * TILE2_BYTES);
    uint32_t* B1w = (uint32_t*)(smem + 3 * TILE2_BYTES);

    int tid = threadIdx.x;
    int wid = tid >> 5, lane = tid & 31;
    int which = blockIdx.y;
    int row0 = blockIdx.x * 128;
    const float* bias = (which == 0) ? b0 : ((which == 1) ? b1 : ((which == 2) ? b2 : b3));
    float* O = (which == 0) ? g_Q : ((which == 1) ? g_K : ((which == 2) ? g_V : g_S));

    int wm = (wid >> 2) * 64;
    int wn = (wid & 3) * 32;
    int g = lane >> 2, tg = lane & 3;

    float c[4][4][4];
#pragma unroll
    for (int mt = 0; mt < 4; mt++)
#pragma unroll
        for (int nt = 0; nt < 4; nt++)
#pragma unroll
            for (int r = 0; r < 4; r++) c[mt][nt][r] = 0.f;

    int arow[4], brow[4];
#pragma unroll
    for (int mt = 0; mt < 4; mt++) arow[mt] = (wm + mt * 16 + g) * WS2;
#pragma unroll
    for (int nt = 0; nt < 4; nt++) brow[nt] = (wn + nt * 8 + g) * WS2;

    const uint4* xa0 = (const uint4*)g_X0;
    const uint4* xa1 = (const uint4*)g_X1;
    size_t wbase = ((size_t)(l * 4 + which)) << 14;
    const uint4* wb0 = (const uint4*)(g_B0 + wbase);
    const uint4* wb1 = (const uint4*)(g_B1 + wbase);
    const uint4 z4 = make_uint4(0u, 0u, 0u, 0u);

#pragma unroll
    for (int kc = 0; kc < 2; kc++) {
#pragma unroll
        for (int it = 0; it < 4; it++) {
            int i = tid + it * 256;          // 0..1023
            int row = i >> 3, c8 = i & 7;    // 8 uint4 chunks per row
            int so = row * (WS2 / 4) + c8;   // uint4 index (9 per padded row)
            bool ok = (row0 + row) < NN;
            size_t gi = (size_t)(row0 + row) * 16 + kc * 8 + c8;
            ((uint4*)A0w)[so] = ok ? xa0[gi] : z4;
            ((uint4*)A1w)[so] = ok ? xa1[gi] : z4;
            size_t bi = (size_t)row * 16 + kc * 8 + c8;
            ((uint4*)B0w)[so] = wb0[bi];
            ((uint4*)B1w)[so] = wb1[bi];
        }
        __syncthreads();

#pragma unroll
        for (int ks = 0; ks < 4; ks++) {
            int kw = ks * 8 + tg;
            uint32_t ah[4][4], bh[4][2], al[4][4], bl[4][2];
#pragma unroll
            for (int mt = 0; mt < 4; mt++) {
                ah[mt][0] = A0w[arow[mt] + kw];
                ah[mt][1] = A0w[arow[mt] + 8 * WS2 + kw];
                ah[mt][2] = A0w[arow[mt] + kw + 4];
                ah[mt][3] = A0w[arow[mt] + 8 * WS2 + kw + 4];
            }
#pragma unroll
            for (int nt = 0; nt < 4; nt++) {
                bh[nt][0] = B0w[brow[nt] + kw];
                bh[nt][1] = B0w[brow[nt] + kw + 4];
            }
#pragma unroll
            for (int mt = 0; mt < 4; mt++)
#pragma unroll
                for (int nt = 0; nt < 4; nt++) mma_bf16(c[mt][nt], ah[mt], bh[nt]);

#pragma unroll
            for (int nt = 0; nt < 4; nt++) {
                bl[nt][0] = B1w[brow[nt] + kw];
                bl[nt][1] = B1w[brow[nt] + kw + 4];
            }
#pragma unroll
            for (int mt = 0; mt < 4; mt++)
#pragma unroll
                for (int nt = 0; nt < 4; nt++) mma_bf16(c[mt][nt], ah[mt], bl[nt]);

#pragma unroll
            for (int mt = 0; mt < 4; mt++) {
                al[mt][0] = A1w[arow[mt] + kw];
                al[mt][1] = A1w[arow[mt] + 8 * WS2 + kw];
                al[mt][2] = A1w[arow[mt] + kw + 4];
                al[mt][3] = A1w[arow[mt] + 8 * WS2 + kw + 4];
            }
#pragma unroll
            for (int mt = 0; mt < 4; mt++)
#pragma unroll
                for (int nt = 0; nt < 4; nt++) mma_bf16(c[mt][nt], al[mt], bh[nt]);
        }
        __syncthreads();
    }

#pragma unroll
    for (int mt = 0; mt < 4; mt++) {
#pragma unroll
        for (int nt = 0; nt < 4; nt++) {
            int col = wn + nt * 8 + tg * 2;
            float bx = bias[col], by = bias[col + 1];
            int row = row0 + wm + mt * 16 + g;
            if (row < NN) {
                float2* p = (float2*)(O + (size_t)row * FF + col);
                *p = make_float2(c[mt][nt][0] + bx, c[mt][nt][1] + by);
            }
            if (row + 8 < NN) {
                float2* p = (float2*)(O + (size_t)(row + 8) * FF + col);
                *p = make_float2(c[mt][nt][2] + bx, c[mt][nt][3] + by);
            }
        }
    }
}

// ---------------- edge phase v3: CSR-ordered staging, single scattered write ----------------
// pass1: K-dot -> stage[p*8+h] (CSR-contiguous) + running max
// pass2: broadcast-load stage, exp off-chain, denom/acc; leader writes pe back to stage
// pass3: coalesced stage read (stage[p0*8+lane]), scale by inv, ONE streaming scattered
//        write to alpha_out[eidx*8+h].
__global__ void __launch_bounds__(256) edge_kernel(
    int final_layer, float* __restrict__ out_h, float* __restrict__ alpha_out)
{
    int gw = (blockIdx.x * blockDim.x + threadIdx.x) >> 5;
    int lane = threadIdx.x & 31;
    if (gw >= NN) return;
    int n = gw;
    int beg = g_rowptr[n];
    int end = g_rowptr[n + 1];

    float4 q4 = ((const float4*)(g_Q + (size_t)n * FF))[lane];
    int h = lane >> 2;

    // ---- pass 1: alphas to stage + max ----
    float m = -3.0e38f;
#pragma unroll 2
    for (int p = beg; p < end; p++) {
        int s = g_srcs[p];
        float4 k4 = ((const float4*)(g_K + (size_t)s * FF))[lane];
        float d = q4.x * k4.x + q4.y * k4.y + q4.z * k4.z + q4.w * k4.w;
        d += __shfl_xor_sync(0xffffffffu, d, 1);
        d += __shfl_xor_sync(0xffffffffu, d, 2);
        float alpha = d * 0.25f;
        if ((lane & 3) == 0) g_stage[(size_t)p * HH + h] = alpha;
        m = fmaxf(m, alpha);
    }
    __syncwarp();   // pass-1 stage stores visible to all lanes

    // ---- pass 2: denom + weighted V accumulation; overwrite stage with pe ----
    float denom = 0.f;
    float4 acc = make_float4(0.f, 0.f, 0.f, 0.f);
#pragma unroll 2
    for (int p = beg; p < end; p++) {
        int s = g_srcs[p];
        float a = g_stage[(size_t)p * HH + h];       // same address per 4-lane group: broadcast
        float pe = __expf(a - m);
        if ((lane & 3) == 0) g_stage[(size_t)p * HH + h] = pe;
        float4 v4 = ((const float4*)(g_V + (size_t)s * FF))[lane];
        denom += pe;
        acc.x += pe * v4.x;
        acc.y += pe * v4.y;
        acc.z += pe * v4.z;
        acc.w += pe * v4.w;
    }

    float inv = (end > beg && denom > 0.f) ? 1.f / denom : 0.f;

    // ---- epilogue: node output ----
    float4 s4 = ((const float4*)(g_S + (size_t)n * FF))[lane];
    float4 o;
    o.x = acc.x * inv + s4.x;
    o.y = acc.y * inv + s4.y;
    o.z = acc.z * inv + s4.z;
    o.w = acc.w * inv + s4.w;
    if (!final_layer) {
        o.x = 0.5f * o.x * (1.f + erff(o.x * 0.70710678118654752f));
        o.y = 0.5f * o.y * (1.f + erff(o.y * 0.70710678118654752f));
        o.z = 0.5f * o.z * (1.f + erff(o.z * 0.70710678118654752f));
        o.w = 0.5f * o.w * (1.f + erff(o.w * 0.70710678118654752f));
        __nv_bfloat16 h0, l0, h1, l1, h2c, l2, h3, l3;
        split_bf16(o.x, h0, l0); split_bf16(o.y, h1, l1);
        split_bf16(o.z, h2c, l2); split_bf16(o.w, h3, l3);
        __nv_bfloat162* p0 = (__nv_bfloat162*)(g_X0 + (size_t)n * FF);
        __nv_bfloat162* p1 = (__nv_bfloat162*)(g_X1 + (size_t)n * FF);
        p0[lane * 2]     = __nv_bfloat162(h0, h1);
        p0[lane * 2 + 1] = __nv_bfloat162(h2c, h3);
        p1[lane * 2]     = __nv_bfloat162(l0, l1);
        p1[lane * 2 + 1] = __nv_bfloat162(l2, l3);
    } else {
        __stcs((float4*)(out_h + (size_t)n * FF) + lane, o);
    }

    // ---- pass 3: coalesced stage read, scale, single scattered streaming write ----
    __syncwarp();   // pass-2 pe stores visible to all lanes
    int h2 = lane & 7;
    float invh = __shfl_sync(0xffffffffu, inv, h2 * 4);
    for (int p0i = beg; p0i < end; p0i += 4) {
        int p = p0i + (lane >> 3);
        if (p < end) {
            float pe = g_stage[(size_t)p0i * HH + lane];   // coalesced 128B per warp
            __stcs(&alpha_out[(size_t)g_eidx[p] * HH + h2], pe * invh);
        }
    }
}

static float* alpha_stage_ptr() {
    void* p = nullptr;
    cudaGetSymbolAddress(&p, g_alpha_stage);
    return (float*)p;
}

// ---------------- launch ----------------
extern "C" void kernel_launch(void* const* d_in, const int* in_sizes, int n_in,
                              void* d_out, int out_size)
{
    const float* x = (const float*)d_in[0];
    const void* ei = (const void*)d_in[1];
    const float* Wq = (const float*)d_in[2];
    const float* bq = (const float*)d_in[3];
    const float* Wk = (const float*)d_in[4];
    const float* bk = (const float*)d_in[5];
    const float* Wv = (const float*)d_in[6];
    const float* bv = (const float*)d_in[7];
    const float* Ws = (const float*)d_in[8];
    const float* bs = (const float*)d_in[9];
    float* out = (float*)d_out;

    cudaFuncSetAttribute(gemm_mma_kernel, cudaFuncAttributeMaxDynamicSharedMemorySize, SMEM2_TOTAL);

    const long long full_elems = (long long)NN * FF + (long long)LL * EE * HH;
    bool alphas_in_out = ((long long)out_size >= full_elems);
    float* stage = alphas_in_out ? nullptr : alpha_stage_ptr();

    detect_kernel<<<1, 1>>>((const int*)ei);
    zero_deg_kernel<<<(NN + 255) / 256, 256>>>();
    hist_kernel<<<(EE + 255) / 256, 256>>>(ei);
    reduce_kernel<<<SCAN_NB, SCAN_B>>>();
    scanpart_kernel<<<1, SCAN_B>>>();
    scanfinal_kernel<<<SCAN_NB, SCAN_B>>>();
    scatter_kernel<<<(EE + 255) / 256, 256>>>(ei);

    splitw_all_kernel<<<(LL * 4 * FF * FF + 255) / 256, 256>>>(Wq, Wk, Wv, Ws);
    splitx_kernel<<<(NN * FF / 4 + 255) / 256, 256>>>(x);

    dim3 ggrid(MTILES, 4);
    int eblocks = (NN * 32 + 255) / 256;

    for (int l = 0; l < LL; l++) {
        size_t bofs = (size_t)l * FF;
        gemm_mma_kernel<<<ggrid, 256, SMEM2_TOTAL>>>(l, bq + bofs, bk + bofs, bv + bofs, bs + bofs);
        float* alpha_out = alphas_in_out
            ? (out + (size_t)NN * FF + (size_t)l * EE * HH)
            : stage;
        edge_kernel<<<eblocks, 256>>>((l == LL - 1) ? 1 : 0, out, alpha_out);
    }
}

// round 16
// speedup vs baseline: 2.2900x; 1.1524x over previous
#include <cuda_runtime.h>
#include <cuda_bf16.h>
#include <math.h>
#include <stdint.h>

#define NN 50000
#define EE 800000
#define FF 128
#define HH 8
#define LL 4

#define SCAN_B 256
#define SCAN_NB ((NN + SCAN_B - 1) / SCAN_B)   // 196
#define MTILES ((NN + 127) / 128)              // 391

// smem tile geometry: 128 rows x 64 bf16 cols (BK=64), padded to 72 (144B rows)
#define SJ2 72
#define WS2 (SJ2 / 2)                          // 36 words per row
#define TILE2_BYTES (128 * SJ2 * 2)            // 18432
#define SMEM2_TOTAL (4 * TILE2_BYTES)          // 73728

// ---------------- scratch (static device allocations; no cudaMalloc) ----------------
__device__ float g_Q[NN * FF];
__device__ float g_K[NN * FF];
__device__ float g_V[NN * FF];
__device__ float g_S[NN * FF];
__device__ float g_stage[EE * HH];                 // CSR-ordered alpha staging (L2-hot)
__device__ float g_alpha_stage[EE * HH];           // fallback final sink if out buffer lacks room
__device__ __nv_bfloat16 g_X0[NN * FF];            // hi split of layer input
__device__ __nv_bfloat16 g_X1[NN * FF];            // lo split
__device__ __nv_bfloat16 g_B0[LL * 4 * FF * FF];   // W^T hi split, [l][which][n][k]
__device__ __nv_bfloat16 g_B1[LL * 4 * FF * FF];   // W^T lo split
__device__ int g_deg[NN];
__device__ int g_rowptr[NN + 1];
__device__ int g_cursor[NN];
__device__ int g_eidx[EE];
__device__ int g_srcs[EE];
__device__ int g_is64;
__device__ int g_blocksum[SCAN_NB];

// ---------------- dtype detection ----------------
__global__ void detect_kernel(const int* __restrict__ ei32) {
    int zeros = 0;
    for (int i = 0; i < 64; i++)
        if (ei32[2 * i + 1] == 0) zeros++;
    g_is64 = (zeros >= 48) ? 1 : 0;
}

__device__ __forceinline__ int load_idx(const void* eiv, long long pos) {
    if (g_is64) return (int)((const long long*)eiv)[pos];
    return ((const int*)eiv)[pos];
}

// ---------------- CSR construction ----------------
__global__ void zero_deg_kernel() {
    int i = blockIdx.x * blockDim.x + threadIdx.x;
    if (i < NN) g_deg[i] = 0;
}

__global__ void hist_kernel(const void* __restrict__ eiv) {
    int e = blockIdx.x * blockDim.x + threadIdx.x;
    if (e < EE) {
        int d = load_idx(eiv, (long long)EE + e);
        if (d >= 0 && d < NN) atomicAdd(&g_deg[d], 1);
    }
}

__global__ void __launch_bounds__(SCAN_B) reduce_kernel() {
    int tid = threadIdx.x, lane = tid & 31, wid = tid >> 5;
    int i = blockIdx.x * SCAN_B + tid;
    int v = (i < NN) ? g_deg[i] : 0;
#pragma unroll
    for (int o = 16; o > 0; o >>= 1) v += __shfl_down_sync(0xffffffffu, v, o);
    __shared__ int ws[8];
    if (lane == 0) ws[wid] = v;
    __syncthreads();
    if (tid == 0) {
        int s = 0;
#pragma unroll
        for (int w = 0; w < 8; w++) s += ws[w];
        g_blocksum[blockIdx.x] = s;
    }
}

__device__ __forceinline__ int block_incl_scan(int v, int tid) {
    int lane = tid & 31, wid = tid >> 5;
    int x = v;
#pragma unroll
    for (int o = 1; o < 32; o <<= 1) {
        int t = __shfl_up_sync(0xffffffffu, x, o);
        if (lane >= o) x += t;
    }
    __shared__ int wsum[8];
    if (lane == 31) wsum[wid] = x;
    __syncthreads();
    if (wid == 0) {
        int y = (lane < 8) ? wsum[lane] : 0;
#pragma unroll
        for (int o = 1; o < 8; o <<= 1) {
            int t = __shfl_up_sync(0xffffffffu, y, o);
            if (lane >= o) y += t;
        }
        if (lane < 8) wsum[lane] = y;
    }
    __syncthreads();
    return x + ((wid > 0) ? wsum[wid - 1] : 0);
}

__global__ void __launch_bounds__(SCAN_B) scanpart_kernel() {
    int tid = threadIdx.x;
    int v = (tid < SCAN_NB) ? g_blocksum[tid] : 0;
    int incl = block_incl_scan(v, tid);
    if (tid < SCAN_NB) g_blocksum[tid] = incl - v;
}

__global__ void __launch_bounds__(SCAN_B) scanfinal_kernel() {
    int tid = threadIdx.x;
    int i = blockIdx.x * SCAN_B + tid;
    int v = (i < NN) ? g_deg[i] : 0;
    int incl = block_incl_scan(v, tid);
    int off = g_blocksum[blockIdx.x];
    if (i < NN) {
        int e = off + incl - v;
        g_rowptr[i] = e;
        g_cursor[i] = e;
    }
    if (i == NN - 1) g_rowptr[NN] = off + incl;
}

__global__ void scatter_kernel(const void* __restrict__ eiv) {
    int e = blockIdx.x * blockDim.x + threadIdx.x;
    if (e < EE) {
        int s = load_idx(eiv, e);
        int d = load_idx(eiv, (long long)EE + e);
        if (d >= 0 && d < NN && s >= 0 && s < NN) {
            int p = atomicAdd(&g_cursor[d], 1);
            if (p >= 0 && p < EE) {
                g_eidx[p] = e;
                g_srcs[p] = s;
            }
        }
    }
}

// ---------------- split helpers (fp32 -> hi/lo bf16) ----------------
__device__ __forceinline__ void split_bf16(float v, __nv_bfloat16& hi, __nv_bfloat16& lo) {
    hi = __float2bfloat16_rn(v);
    lo = __float2bfloat16_rn(v - __bfloat162float(hi));
}

__global__ void __launch_bounds__(256) splitx_kernel(const float* __restrict__ X) {
    int i = blockIdx.x * blockDim.x + threadIdx.x;   // float4 index
    if (i < NN * FF / 4) {
        float4 v = ((const float4*)X)[i];
        __nv_bfloat16 h0, l0, h1, l1, h2, l2, h3, l3;
        split_bf16(v.x, h0, l0); split_bf16(v.y, h1, l1);
        split_bf16(v.z, h2, l2); split_bf16(v.w, h3, l3);
        ((__nv_bfloat162*)g_X0)[2 * i]     = __nv_bfloat162(h0, h1);
        ((__nv_bfloat162*)g_X0)[2 * i + 1] = __nv_bfloat162(h2, h3);
        ((__nv_bfloat162*)g_X1)[2 * i]     = __nv_bfloat162(l0, l1);
        ((__nv_bfloat162*)g_X1)[2 * i + 1] = __nv_bfloat162(l2, l3);
    }
}

__global__ void __launch_bounds__(256) splitw_all_kernel(
    const float* __restrict__ Wq, const float* __restrict__ Wk,
    const float* __restrict__ Wv, const float* __restrict__ Ws)
{
    int idx = blockIdx.x * blockDim.x + threadIdx.x;   // l*65536 + which*16384 + k*128 + n
    if (idx < LL * 4 * FF * FF) {
        int l = idx >> 16;
        int which = (idx >> 14) & 3;
        int r = idx & 16383;
        int k = r >> 7, n = r & 127;
        const float* W = (which == 0) ? Wq : ((which == 1) ? Wk : ((which == 2) ? Wv : Ws));
        float v = W[(size_t)l * FF * FF + r];
        __nv_bfloat16 hi, lo;
        split_bf16(v, hi, lo);
        size_t base = ((size_t)(l * 4 + which)) << 14;
        g_B0[base + n * FF + k] = hi;
        g_B1[base + n * FF + k] = lo;
    }
}

// ---------------- bf16 mma.sync GEMM: O = X @ W + b via 3-product split ----------------
__device__ __forceinline__ void mma_bf16(float* c, const uint32_t* a, const uint32_t* b) {
    asm volatile(
        "mma.sync.aligned.m16n8k16.row.col.f32.bf16.bf16.f32 "
        "{%0,%1,%2,%3}, {%4,%5,%6,%7}, {%8,%9}, {%0,%1,%2,%3};"
        : "+f"(c[0]), "+f"(c[1]), "+f"(c[2]), "+f"(c[3])
        : "r"(a[0]), "r"(a[1]), "r"(a[2]), "r"(a[3]), "r"(b[0]), "r"(b[1]));
}

// grid (MTILES, 4), 256 threads, BK=64 x 2 steps, 73.7 KB smem -> 2 CTAs/SM.
__global__ void __launch_bounds__(256, 2) gemm_mma_kernel(
    int l,
    const float* __restrict__ b0, const float* __restrict__ b1,
    const float* __restrict__ b2, const float* __restrict__ b3)
{
    extern __shared__ char smem[];
    uint32_t* A0w = (uint32_t*)smem;
    uint32_t* A1w = (uint32_t*)(smem + TILE2_BYTES);
    uint32_t* B0w = (uint32_t*)(smem + 2 * TILE2_BYTES);
    uint32_t* B1w = (uint32_t*)(smem + 3 * TILE2_BYTES);

    int tid = threadIdx.x;
    int wid = tid >> 5, lane = tid & 31;
    int which = blockIdx.y;
    int row0 = blockIdx.x * 128;
    const float* bias = (which == 0) ? b0 : ((which == 1) ? b1 : ((which == 2) ? b2 : b3));
    float* O = (which == 0) ? g_Q : ((which == 1) ? g_K : ((which == 2) ? g_V : g_S));

    int wm = (wid >> 2) * 64;
    int wn = (wid & 3) * 32;
    int g = lane >> 2, tg = lane & 3;

    float c[4][4][4];
#pragma unroll
    for (int mt = 0; mt < 4; mt++)
#pragma unroll
        for (int nt = 0; nt < 4; nt++)
#pragma unroll
            for (int r = 0; r < 4; r++) c[mt][nt][r] = 0.f;

    int arow[4], brow[4];
#pragma unroll
    for (int mt = 0; mt < 4; mt++) arow[mt] = (wm + mt * 16 + g) * WS2;
#pragma unroll
    for (int nt = 0; nt < 4; nt++) brow[nt] = (wn + nt * 8 + g) * WS2;

    const uint4* xa0 = (const uint4*)g_X0;
    const uint4* xa1 = (const uint4*)g_X1;
    size_t wbase = ((size_t)(l * 4 + which)) << 14;
    const uint4* wb0 = (const uint4*)(g_B0 + wbase);
    const uint4* wb1 = (const uint4*)(g_B1 + wbase);
    const uint4 z4 = make_uint4(0u, 0u, 0u, 0u);

#pragma unroll
    for (int kc = 0; kc < 2; kc++) {
#pragma unroll
        for (int it = 0; it < 4; it++) {
            int i = tid + it * 256;          // 0..1023
            int row = i >> 3, c8 = i & 7;    // 8 uint4 chunks per row
            int so = row * (WS2 / 4) + c8;   // uint4 index (9 per padded row)
            bool ok = (row0 + row) < NN;
            size_t gi = (size_t)(row0 + row) * 16 + kc * 8 + c8;
            ((uint4*)A0w)[so] = ok ? xa0[gi] : z4;
            ((uint4*)A1w)[so] = ok ? xa1[gi] : z4;
            size_t bi = (size_t)row * 16 + kc * 8 + c8;
            ((uint4*)B0w)[so] = wb0[bi];
            ((uint4*)B1w)[so] = wb1[bi];
        }
        __syncthreads();

#pragma unroll
        for (int ks = 0; ks < 4; ks++) {
            int kw = ks * 8 + tg;
            uint32_t ah[4][4], bh[4][2], al[4][4], bl[4][2];
#pragma unroll
            for (int mt = 0; mt < 4; mt++) {
                ah[mt][0] = A0w[arow[mt] + kw];
                ah[mt][1] = A0w[arow[mt] + 8 * WS2 + kw];
                ah[mt][2] = A0w[arow[mt] + kw + 4];
                ah[mt][3] = A0w[arow[mt] + 8 * WS2 + kw + 4];
            }
#pragma unroll
            for (int nt = 0; nt < 4; nt++) {
                bh[nt][0] = B0w[brow[nt] + kw];
                bh[nt][1] = B0w[brow[nt] + kw + 4];
            }
#pragma unroll
            for (int mt = 0; mt < 4; mt++)
#pragma unroll
                for (int nt = 0; nt < 4; nt++) mma_bf16(c[mt][nt], ah[mt], bh[nt]);

#pragma unroll
            for (int nt = 0; nt < 4; nt++) {
                bl[nt][0] = B1w[brow[nt] + kw];
                bl[nt][1] = B1w[brow[nt] + kw + 4];
            }
#pragma unroll
            for (int mt = 0; mt < 4; mt++)
#pragma unroll
                for (int nt = 0; nt < 4; nt++) mma_bf16(c[mt][nt], ah[mt], bl[nt]);

#pragma unroll
            for (int mt = 0; mt < 4; mt++) {
                al[mt][0] = A1w[arow[mt] + kw];
                al[mt][1] = A1w[arow[mt] + 8 * WS2 + kw];
                al[mt][2] = A1w[arow[mt] + kw + 4];
                al[mt][3] = A1w[arow[mt] + 8 * WS2 + kw + 4];
            }
#pragma unroll
            for (int mt = 0; mt < 4; mt++)
#pragma unroll
                for (int nt = 0; nt < 4; nt++) mma_bf16(c[mt][nt], al[mt], bh[nt]);
        }
        __syncthreads();
    }

#pragma unroll
    for (int mt = 0; mt < 4; mt++) {
#pragma unroll
        for (int nt = 0; nt < 4; nt++) {
            int col = wn + nt * 8 + tg * 2;
            float bx = bias[col], by = bias[col + 1];
            int row = row0 + wm + mt * 16 + g;
            if (row < NN) {
                float2* p = (float2*)(O + (size_t)row * FF + col);
                *p = make_float2(c[mt][nt][0] + bx, c[mt][nt][1] + by);
            }
            if (row + 8 < NN) {
                float2* p = (float2*)(O + (size_t)(row + 8) * FF + col);
                *p = make_float2(c[mt][nt][2] + bx, c[mt][nt][3] + by);
            }
        }
    }
}

// ---------------- edge phase v4: CSR staging + manual 2x unrolled gathers ----------------
__device__ __forceinline__ float dot4(float4 a, float4 b) {
    return a.x * b.x + a.y * b.y + a.z * b.z + a.w * b.w;
}

__global__ void __launch_bounds__(256) edge_kernel(
    int final_layer, float* __restrict__ out_h, float* __restrict__ alpha_out)
{
    int gw = (blockIdx.x * blockDim.x + threadIdx.x) >> 5;
    int lane = threadIdx.x & 31;
    if (gw >= NN) return;
    int n = gw;
    int beg = g_rowptr[n];
    int end = g_rowptr[n + 1];

    float4 q4 = ((const float4*)(g_Q + (size_t)n * FF))[lane];
    int h = lane >> 2;

    // ---- pass 1: alphas to stage + max (2 edges in flight) ----
    float m = -3.0e38f;
    int p = beg;
    for (; p + 2 <= end; p += 2) {
        int s0 = g_srcs[p], s1 = g_srcs[p + 1];
        float4 k0 = ((const float4*)(g_K + (size_t)s0 * FF))[lane];
        float4 k1 = ((const float4*)(g_K + (size_t)s1 * FF))[lane];
        float d0 = dot4(q4, k0);
        float d1 = dot4(q4, k1);
        d0 += __shfl_xor_sync(0xffffffffu, d0, 1);
        d1 += __shfl_xor_sync(0xffffffffu, d1, 1);
        d0 += __shfl_xor_sync(0xffffffffu, d0, 2);
        d1 += __shfl_xor_sync(0xffffffffu, d1, 2);
        float a0 = d0 * 0.25f, a1 = d1 * 0.25f;
        if ((lane & 3) == 0) {
            g_stage[(size_t)p * HH + h] = a0;
            g_stage[(size_t)(p + 1) * HH + h] = a1;
        }
        m = fmaxf(m, fmaxf(a0, a1));
    }
    if (p < end) {
        int s = g_srcs[p];
        float4 k4 = ((const float4*)(g_K + (size_t)s * FF))[lane];
        float d = dot4(q4, k4);
        d += __shfl_xor_sync(0xffffffffu, d, 1);
        d += __shfl_xor_sync(0xffffffffu, d, 2);
        float alpha = d * 0.25f;
        if ((lane & 3) == 0) g_stage[(size_t)p * HH + h] = alpha;
        m = fmaxf(m, alpha);
    }
    __syncwarp();

    // ---- pass 2: denom + weighted V (2 edges in flight); overwrite stage with pe ----
    float denom = 0.f;
    float4 acc = make_float4(0.f, 0.f, 0.f, 0.f);
    p = beg;
    for (; p + 2 <= end; p += 2) {
        int s0 = g_srcs[p], s1 = g_srcs[p + 1];
        float a0 = g_stage[(size_t)p * HH + h];
        float a1 = g_stage[(size_t)(p + 1) * HH + h];
        float4 v0 = ((const float4*)(g_V + (size_t)s0 * FF))[lane];
        float4 v1 = ((const float4*)(g_V + (size_t)s1 * FF))[lane];
        float pe0 = __expf(a0 - m);
        float pe1 = __expf(a1 - m);
        if ((lane & 3) == 0) {
            g_stage[(size_t)p * HH + h] = pe0;
            g_stage[(size_t)(p + 1) * HH + h] = pe1;
        }
        denom += pe0 + pe1;
        acc.x += pe0 * v0.x + pe1 * v1.x;
        acc.y += pe0 * v0.y + pe1 * v1.y;
        acc.z += pe0 * v0.z + pe1 * v1.z;
        acc.w += pe0 * v0.w + pe1 * v1.w;
    }
    if (p < end) {
        int s = g_srcs[p];
        float a = g_stage[(size_t)p * HH + h];
        float pe = __expf(a - m);
        if ((lane & 3) == 0) g_stage[(size_t)p * HH + h] = pe;
        float4 v4 = ((const float4*)(g_V + (size_t)s * FF))[lane];
        denom += pe;
        acc.x += pe * v4.x;
        acc.y += pe * v4.y;
        acc.z += pe * v4.z;
        acc.w += pe * v4.w;
    }

    float inv = (end > beg && denom > 0.f) ? 1.f / denom : 0.f;

    // ---- epilogue: node output ----
    float4 s4 = ((const float4*)(g_S + (size_t)n * FF))[lane];
    float4 o;
    o.x = acc.x * inv + s4.x;
    o.y = acc.y * inv + s4.y;
    o.z = acc.z * inv + s4.z;
    o.w = acc.w * inv + s4.w;
    if (!final_layer) {
        o.x = 0.5f * o.x * (1.f + erff(o.x * 0.70710678118654752f));
        o.y = 0.5f * o.y * (1.f + erff(o.y * 0.70710678118654752f));
        o.z = 0.5f * o.z * (1.f + erff(o.z * 0.70710678118654752f));
        o.w = 0.5f * o.w * (1.f + erff(o.w * 0.70710678118654752f));
        __nv_bfloat16 h0, l0, h1, l1, h2c, l2, h3, l3;
        split_bf16(o.x, h0, l0); split_bf16(o.y, h1, l1);
        split_bf16(o.z, h2c, l2); split_bf16(o.w, h3, l3);
        __nv_bfloat162* p0 = (__nv_bfloat162*)(g_X0 + (size_t)n * FF);
        __nv_bfloat162* p1 = (__nv_bfloat162*)(g_X1 + (size_t)n * FF);
        p0[lane * 2]     = __nv_bfloat162(h0, h1);
        p0[lane * 2 + 1] = __nv_bfloat162(h2c, h3);
        p1[lane * 2]     = __nv_bfloat162(l0, l1);
        p1[lane * 2 + 1] = __nv_bfloat162(l2, l3);
    } else {
        __stcs((float4*)(out_h + (size_t)n * FF) + lane, o);
    }

    // ---- pass 3: coalesced stage read, scale, single scattered streaming write ----
    __syncwarp();
    int h2 = lane & 7;
    float invh = __shfl_sync(0xffffffffu, inv, h2 * 4);
    for (int p0i = beg; p0i < end; p0i += 4) {
        int pp = p0i + (lane >> 3);
        if (pp < end) {
            float pe = g_stage[(size_t)p0i * HH + lane];   // coalesced 128B per warp
            __stcs(&alpha_out[(size_t)g_eidx[pp] * HH + h2], pe * invh);
        }
    }
}

static float* alpha_stage_ptr() {
    void* p = nullptr;
    cudaGetSymbolAddress(&p, g_alpha_stage);
    return (float*)p;
}

// ---------------- launch ----------------
extern "C" void kernel_launch(void* const* d_in, const int* in_sizes, int n_in,
                              void* d_out, int out_size)
{
    const float* x = (const float*)d_in[0];
    const void* ei = (const void*)d_in[1];
    const float* Wq = (const float*)d_in[2];
    const float* bq = (const float*)d_in[3];
    const float* Wk = (const float*)d_in[4];
    const float* bk = (const float*)d_in[5];
    const float* Wv = (const float*)d_in[6];
    const float* bv = (const float*)d_in[7];
    const float* Ws = (const float*)d_in[8];
    const float* bs = (const float*)d_in[9];
    float* out = (float*)d_out;

    cudaFuncSetAttribute(gemm_mma_kernel, cudaFuncAttributeMaxDynamicSharedMemorySize, SMEM2_TOTAL);

    // static side stream + fork/join events (created once on the first,
    // non-captured correctness call; reused inside graph capture afterwards)
    static cudaStream_t s_side = nullptr;
    static cudaEvent_t s_fork = nullptr, s_join = nullptr;
    if (s_side == nullptr) {
        cudaStreamCreateWithFlags(&s_side, cudaStreamNonBlocking);
        cudaEventCreateWithFlags(&s_fork, cudaEventDisableTiming);
        cudaEventCreateWithFlags(&s_join, cudaEventDisableTiming);
    }

    const long long full_elems = (long long)NN * FF + (long long)LL * EE * HH;
    bool alphas_in_out = ((long long)out_size >= full_elems);
    float* stage = alphas_in_out ? nullptr : alpha_stage_ptr();

    // ---- fork: CSR build on side stream, splits + gemm0 on main stream ----
    cudaEventRecord(s_fork, 0);
    cudaStreamWaitEvent(s_side, s_fork, 0);

    detect_kernel<<<1, 1, 0, s_side>>>((const int*)ei);
    zero_deg_kernel<<<(NN + 255) / 256, 256, 0, s_side>>>();
    hist_kernel<<<(EE + 255) / 256, 256, 0, s_side>>>(ei);
    reduce_kernel<<<SCAN_NB, SCAN_B, 0, s_side>>>();
    scanpart_kernel<<<1, SCAN_B, 0, s_side>>>();
    scanfinal_kernel<<<SCAN_NB, SCAN_B, 0, s_side>>>();
    scatter_kernel<<<(EE + 255) / 256, 256, 0, s_side>>>(ei);
    cudaEventRecord(s_join, s_side);

    splitw_all_kernel<<<(LL * 4 * FF * FF + 255) / 256, 256>>>(Wq, Wk, Wv, Ws);
    splitx_kernel<<<(NN * FF / 4 + 255) / 256, 256>>>(x);

    dim3 ggrid(MTILES, 4);
    int eblocks = (NN * 32 + 255) / 256;

    for (int l = 0; l < LL; l++) {
        size_t bofs = (size_t)l * FF;
        gemm_mma_kernel<<<ggrid, 256, SMEM2_TOTAL>>>(l, bq + bofs, bk + bofs, bv + bofs, bs + bofs);
        if (l == 0) cudaStreamWaitEvent(0, s_join, 0);   // CSR must be ready before first edge pass
        float* alpha_out = alphas_in_out
            ? (out + (size_t)NN * FF + (size_t)l * EE * HH)
            : stage;
        edge_kernel<<<eblocks, 256>>>((l == LL - 1) ? 1 : 0, out, alpha_out);
    }
}